// round 1
// baseline (speedup 1.0000x reference)
#include <cuda_runtime.h>
#include <cstdint>

#define Mdim 512
#define Cdim 256
#define Bdim 8
#define Tdim 32
#define BT 256            // B*T
#define MC 131072         // M*C
#define TOPKK 8
#define LAMf 0.05f
#define RHOf 0.9f
#define DLRf 0.03f
#define EPSF 1e-12f
#define LN_EPSF 1e-5f
#define AP 776            // padded A row pitch (floats)
#define NTILE 32          // C / 8 column tiles
#define CPT 8             // columns per tile
#define CPITCH 520        // smem cand pitch

// ---------------- scratch (device globals; no allocation allowed) ----------
__device__ float g_LNu[BT * Mdim];                 // LN(u) rows
__device__ float g_A[BT * AP];                     // GEMM A: [u(512) | c_t(256)]
__device__ float g_Lu[BT * Cdim];                  // LN(u) @ W_cu^T
__device__ float g_ct[BT * Cdim];                  // c_t trajectory
__device__ int   g_aidx[BT * TOPKK];
__device__ float g_aval[BT * TOPKK];
__device__ float g_cand[(size_t)BT * MC];          // 128 MiB cand scratch
__device__ float g_D[2][Bdim * Cdim * Mdim];       // ping-pong dictionary [b][c][m]
__device__ float g_zpart[(size_t)BT * NTILE * Mdim];

// ---------------- helpers --------------------------------------------------
__device__ __forceinline__ float blockReduceSum(float v, float* sh) {
    __syncthreads();                        // protect sh reuse
    #pragma unroll
    for (int o = 16; o; o >>= 1) v += __shfl_xor_sync(0xffffffffu, v, o);
    int w = threadIdx.x >> 5, l = threadIdx.x & 31;
    if (l == 0) sh[w] = v;
    __syncthreads();
    if (w == 0) {
        float x = (l < (int)(blockDim.x >> 5)) ? sh[l] : 0.f;
        #pragma unroll
        for (int o = 4; o; o >>= 1) x += __shfl_xor_sync(0xffffffffu, x, o);
        if (l == 0) sh[0] = x;
    }
    __syncthreads();
    return sh[0];
}

// ---------------- K1: LN(u) for all rows, fill A u-part --------------------
__global__ void k1_lnu(const float* __restrict__ u,
                       const float* __restrict__ g, const float* __restrict__ bb) {
    __shared__ float sh[8];
    int r = blockIdx.x, tid = threadIdx.x;
    const float* ur = u + (size_t)r * Mdim;
    float x0 = ur[tid], x1 = ur[tid + 256];
    float s = blockReduceSum(x0 + x1, sh);
    float mu = s * (1.f / Mdim);
    float d0 = x0 - mu, d1 = x1 - mu;
    float var = blockReduceSum(d0 * d0 + d1 * d1, sh) * (1.f / Mdim);
    float inv = rsqrtf(var + LN_EPSF);
    g_LNu[(size_t)r * Mdim + tid]       = d0 * inv * g[tid] + bb[tid];
    g_LNu[(size_t)r * Mdim + tid + 256] = d1 * inv * g[tid + 256] + bb[tid + 256];
    g_A[(size_t)r * AP + tid]       = x0;
    g_A[(size_t)r * AP + tid + 256] = x1;
}

// ---------------- K2: Lu = LN(u) @ W_cu^T ---------------------------------
__global__ void k2_lu(const float* __restrict__ Wcu) {
    __shared__ float ln[Mdim];
    int r = blockIdx.x, c = threadIdx.x;
    ln[c]       = g_LNu[(size_t)r * Mdim + c];
    ln[c + 256] = g_LNu[(size_t)r * Mdim + c + 256];
    __syncthreads();
    const float4* wr = (const float4*)(Wcu + (size_t)c * Mdim);
    float acc = 0.f;
    #pragma unroll 8
    for (int i = 0; i < 128; i++) {
        float4 w = wr[i];
        acc += w.x * ln[4*i] + w.y * ln[4*i+1] + w.z * ln[4*i+2] + w.w * ln[4*i+3];
    }
    g_Lu[r * Cdim + c] = acc;
}

// ---------------- K3: sequential sparse-code recurrence (per-batch) -------
__global__ void k3_rec(const float* __restrict__ Wcc, const float* __restrict__ valid,
                       const float* __restrict__ lncg, const float* __restrict__ lncb) {
    __shared__ float sh[8];
    __shared__ float cprev[Cdim], lnc[Cdim], sarr[Cdim], sval[Cdim], aD[Cdim];
    __shared__ float wv[8];
    __shared__ int   wi[8];
    int b = blockIdx.x, c = threadIdx.x;
    cprev[c] = 0.f;
    __syncthreads();
    for (int t = 0; t < Tdim; t++) {
        int bt = b * Tdim + t;
        float cp = cprev[c];
        float s  = blockReduceSum(cp, sh);
        float mu = s * (1.f / Cdim);
        float d  = cp - mu;
        float var = blockReduceSum(d * d, sh) * (1.f / Cdim);
        lnc[c] = d * rsqrtf(var + LN_EPSF) * lncg[c] + lncb[c];
        __syncthreads();
        const float4* wr = (const float4*)(Wcc + (size_t)c * Cdim);
        float acc = g_Lu[bt * Cdim + c];
        #pragma unroll 8
        for (int i = 0; i < 64; i++) {
            float4 w = wr[i];
            acc += w.x * lnc[4*i] + w.y * lnc[4*i+1] + w.z * lnc[4*i+2] + w.w * lnc[4*i+3];
        }
        float aa  = fabsf(acc) - LAMf;
        float shr = aa > 0.f ? copysignf(aa, acc) : 0.f;
        sarr[c] = shr; sval[c] = fabsf(shr); aD[c] = 0.f;
        __syncthreads();
        // top-8 via 8 argmax passes (tie -> lowest index, matches lax.top_k)
        for (int k = 0; k < TOPKK; k++) {
            float v = sval[c]; int idx = c;
            #pragma unroll
            for (int o = 16; o; o >>= 1) {
                float ov = __shfl_xor_sync(0xffffffffu, v, o);
                int   oi = __shfl_xor_sync(0xffffffffu, idx, o);
                if (ov > v || (ov == v && oi < idx)) { v = ov; idx = oi; }
            }
            int w = c >> 5;
            if ((c & 31) == 0) { wv[w] = v; wi[w] = idx; }
            __syncthreads();
            if (c == 0) {
                float bv = wv[0]; int bi = wi[0];
                #pragma unroll
                for (int j = 1; j < 8; j++)
                    if (wv[j] > bv || (wv[j] == bv && wi[j] < bi)) { bv = wv[j]; bi = wi[j]; }
                aD[bi] = sarr[bi];
                g_aidx[bt * TOPKK + k] = bi;
                g_aval[bt * TOPKK + k] = sarr[bi];
                sval[bi] = -1.f;
            }
            __syncthreads();
        }
        float v  = valid[bt];
        float cn = RHOf * cp + (1.f - RHOf) * aD[c];
        float ct = v * cn + (1.f - v) * cp;
        g_ct[bt * Cdim + c] = ct;
        g_A[(size_t)bt * AP + Mdim + c] = ct;
        cprev[c] = ct;
        __syncthreads();
    }
}

// ---------------- K4: big cand GEMM (256 x 131072 x 768, fp32, f32x2) -----
__global__ void __launch_bounds__(256, 2)
k4_gemm(const float* __restrict__ Wu, const float* __restrict__ Wc,
        const float* __restrict__ bu, const float* __restrict__ bc) {
    __shared__ float Asm[16][132];
    __shared__ float Wsm[16][132];
    int tid = threadIdx.x;
    int tx = tid & 15, ty = tid >> 4;
    int n0 = blockIdx.x * 128;
    int r0 = blockIdx.y * 128;
    unsigned long long acc[8][4];
    #pragma unroll
    for (int i = 0; i < 8; i++)
        #pragma unroll
        for (int j = 0; j < 4; j++) acc[i][j] = 0ULL;
    int lrow = tid >> 2, lj = (tid & 3) * 4;
    for (int q = 0; q < 48; q++) {
        int k0 = q * 16;
        const float* Wp; int sw;
        if (k0 < 512) { Wp = Wu + k0; sw = 512; } else { Wp = Wc + (k0 - 512); sw = 256; }
        #pragma unroll
        for (int h = 0; h < 128; h += 64) {
            int n = n0 + h + lrow;
            float4 wvv = *(const float4*)(Wp + (size_t)n * sw + lj);
            Wsm[lj+0][h+lrow] = wvv.x; Wsm[lj+1][h+lrow] = wvv.y;
            Wsm[lj+2][h+lrow] = wvv.z; Wsm[lj+3][h+lrow] = wvv.w;
            int r = r0 + h + lrow;
            float4 av = *(const float4*)(g_A + (size_t)r * AP + k0 + lj);
            Asm[lj+0][h+lrow] = av.x; Asm[lj+1][h+lrow] = av.y;
            Asm[lj+2][h+lrow] = av.z; Asm[lj+3][h+lrow] = av.w;
        }
        __syncthreads();
        #pragma unroll
        for (int kk = 0; kk < 16; kk++) {
            float4 a0 = *(const float4*)&Asm[kk][ty * 4];
            float4 a1 = *(const float4*)&Asm[kk][64 + ty * 4];
            float4 w0 = *(const float4*)&Wsm[kk][tx * 4];
            float4 w1 = *(const float4*)&Wsm[kk][64 + tx * 4];
            unsigned long long wp[4];
            asm("mov.b64 %0, {%1,%2};" : "=l"(wp[0]) : "f"(w0.x), "f"(w0.y));
            asm("mov.b64 %0, {%1,%2};" : "=l"(wp[1]) : "f"(w0.z), "f"(w0.w));
            asm("mov.b64 %0, {%1,%2};" : "=l"(wp[2]) : "f"(w1.x), "f"(w1.y));
            asm("mov.b64 %0, {%1,%2};" : "=l"(wp[3]) : "f"(w1.z), "f"(w1.w));
            float aval[8] = {a0.x, a0.y, a0.z, a0.w, a1.x, a1.y, a1.z, a1.w};
            #pragma unroll
            for (int i = 0; i < 8; i++) {
                unsigned long long ap;
                asm("mov.b64 %0, {%1,%1};" : "=l"(ap) : "f"(aval[i]));
                #pragma unroll
                for (int j = 0; j < 4; j++)
                    asm("fma.rn.f32x2 %0, %1, %2, %0;" : "+l"(acc[i][j]) : "l"(ap), "l"(wp[j]));
            }
        }
        __syncthreads();
    }
    // epilogue: unpack, add biases, store
    float4 bua = *(const float4*)(bu + n0 + tx * 4);
    float4 bca = *(const float4*)(bc + n0 + tx * 4);
    float4 bub = *(const float4*)(bu + n0 + 64 + tx * 4);
    float4 bcb = *(const float4*)(bc + n0 + 64 + tx * 4);
    float4 bia = make_float4(bua.x + bca.x, bua.y + bca.y, bua.z + bca.z, bua.w + bca.w);
    float4 bib = make_float4(bub.x + bcb.x, bub.y + bcb.y, bub.z + bcb.z, bub.w + bcb.w);
    #pragma unroll
    for (int i = 0; i < 8; i++) {
        int r = r0 + ((i < 4) ? (ty * 4 + i) : (64 + ty * 4 + (i - 4)));
        float o[8];
        #pragma unroll
        for (int j = 0; j < 4; j++) {
            float lo, hi;
            asm("mov.b64 {%0,%1}, %2;" : "=f"(lo), "=f"(hi) : "l"(acc[i][j]));
            o[2*j] = lo; o[2*j+1] = hi;
        }
        float4 v0 = make_float4(o[0] + bia.x, o[1] + bia.y, o[2] + bia.z, o[3] + bia.w);
        float4 v1 = make_float4(o[4] + bib.x, o[5] + bib.y, o[6] + bib.z, o[7] + bib.w);
        *(float4*)(g_cand + (size_t)r * MC + n0 + tx * 4)      = v0;
        *(float4*)(g_cand + (size_t)r * MC + n0 + 64 + tx * 4) = v1;
    }
}

// ---------------- K5: D0 = normalize_dim1(base), broadcast over b ---------
__global__ void k5_dinit(const float* __restrict__ base) {
    __shared__ float sh[8];
    int c = blockIdx.x, tid = threadIdx.x;  // 128 threads
    float s = 0.f;
    for (int m = tid; m < Mdim; m += 128) {
        float v = base[(size_t)m * Cdim + c];
        s += v * v;
    }
    float stot = blockReduceSum(s, sh);
    float inv = 1.f / fmaxf(sqrtf(stot), EPSF);
    for (int b = 0; b < Bdim; b++)
        for (int m = tid; m < Mdim; m += 128)
            g_D[0][((size_t)b * Cdim + c) * Mdim + m] = base[(size_t)m * Cdim + c] * inv;
}

// ---------------- K6: per-step dictionary update + z partials --------------
__global__ void __launch_bounds__(256)
k_step(int t, int sb,
       const float* __restrict__ u, const float* __restrict__ valid,
       const float* __restrict__ Wg, const float* __restrict__ bg) {
    __shared__ float sh[8];
    __shared__ float rsh[Mdim];
    __shared__ float ctsh[Cdim];
    __shared__ float cnd[CPT][CPITCH];
    __shared__ int   aidx[TOPKK];
    __shared__ float aval[TOPKK];
    __shared__ float gsh;
    const float* Dsrc = g_D[sb];
    float*       Ddst = g_D[sb ^ 1];
    int tile = blockIdx.x, b = blockIdx.y, tid = threadIdx.x;
    int bt = b * Tdim + t;
    int c0 = tile * CPT;
    const float* ur = u + (size_t)bt * Mdim;
    float vv = valid[bt];
    ctsh[tid] = g_ct[bt * Cdim + tid];
    if (tid < TOPKK) { aidx[tid] = g_aidx[bt * TOPKK + tid]; aval[tid] = g_aval[bt * TOPKK + tid]; }
    __syncthreads();
    // residual r = u - D a  (redundant per block), gate partials
    float perr = 0.f, pg = 0.f;
    #pragma unroll
    for (int h = 0; h < 2; h++) {
        int m = tid + h * 256;
        float acc = ur[m];
        #pragma unroll
        for (int j = 0; j < TOPKK; j++)
            acc -= Dsrc[((size_t)b * Cdim + aidx[j]) * Mdim + m] * aval[j];
        rsh[m] = acc;
        perr += acc * acc;
        pg   += Wg[m] * ur[m];
    }
    pg += Wg[Mdim + tid] * ctsh[tid];
    // stage cand tile [8 cols][512 m] transposed in smem (coalesced 32B sectors)
    const float* cb = g_cand + (size_t)bt * MC + c0;
    for (int i = tid; i < Mdim * CPT; i += 256) {
        int mm = i >> 3, j = i & 7;
        cnd[j][mm] = cb[(size_t)mm * Cdim + j];
    }
    float errsum = blockReduceSum(perr, sh);
    float gsum   = blockReduceSum(pg, sh);
    if (tid == 0) {
        float err = sqrtf(errsum);
        float gp  = gsum + Wg[Mdim + Cdim] * err + bg[0];
        gsh = 1.f / (1.f + expf(-gp));
    }
    __syncthreads();
    float g = gsh;
    int w = tid >> 5, lane = tid & 31;
    int cc = c0 + w;
    float av = 0.f;
    #pragma unroll
    for (int j = 0; j < TOPKK; j++)
        if (aidx[j] == cc) av = aval[j];
    const float* Dc = Dsrc + ((size_t)b * Cdim + cc) * Mdim;
    float*       Do = Ddst + ((size_t)b * Cdim + cc) * Mdim;
    float Dreg[16];
    float sl = 0.f, sc2 = 0.f, sx = 0.f;
    float dla = DLRf * av;
    #pragma unroll
    for (int k = 0; k < 16; k++) {
        int m = lane + 32 * k;
        float dd = Dc[m]; Dreg[k] = dd;
        float dl = fmaf(dla, rsh[m], dd);
        float cn = cnd[w][m];
        sl  = fmaf(dl, dl, sl);
        sc2 = fmaf(cn, cn, sc2);
        sx  = fmaf(dl, cn, sx);
    }
    #pragma unroll
    for (int o = 16; o; o >>= 1) {
        sl  += __shfl_xor_sync(0xffffffffu, sl,  o);
        sc2 += __shfl_xor_sync(0xffffffffu, sc2, o);
        sx  += __shfl_xor_sync(0xffffffffu, sx,  o);
    }
    float il  = 1.f / fmaxf(sqrtf(sl),  EPSF);
    float icn = 1.f / fmaxf(sqrtf(sc2), EPSF);
    float w1 = (1.f - g) * il, w2 = g * icn;
    float smix = w1 * w1 * sl + 2.f * w1 * w2 * sx + w2 * w2 * sc2;
    float imix = 1.f / fmaxf(sqrtf(smix), EPSF);
    float ctc = ctsh[cc];
    #pragma unroll
    for (int k = 0; k < 16; k++) {
        int m = lane + 32 * k;
        float dl  = fmaf(dla, rsh[m], Dreg[k]);
        float cn  = cnd[w][m];
        float mix = w1 * dl + w2 * cn;
        float dn  = vv * (mix * imix) + (1.f - vv) * Dreg[k];
        Do[m] = dn;
        cnd[w][m] = dn * ctc;     // z contribution, summed below
    }
    __syncthreads();
    float* zp = g_zpart + ((size_t)bt * NTILE + tile) * Mdim;
    for (int m = tid; m < Mdim; m += 256) {
        float z = 0.f;
        #pragma unroll
        for (int j = 0; j < CPT; j++) z += cnd[j][m];
        zp[m] = z;
    }
}

// ---------------- K7: reduce z partials -> output --------------------------
__global__ void k_out(float* __restrict__ out) {
    int gi = blockIdx.x * 256 + threadIdx.x;   // < BT * M
    int bt = gi >> 9, m = gi & 511;
    const float* zp = g_zpart + (size_t)bt * NTILE * Mdim + m;
    float s = 0.f;
    #pragma unroll
    for (int j = 0; j < NTILE; j++) s += zp[(size_t)j * Mdim];
    out[gi] = s;
}

// ---------------- launch ---------------------------------------------------
extern "C" void kernel_launch(void* const* d_in, const int* in_sizes, int n_in,
                              void* d_out, int out_size) {
    const float* u       = (const float*)d_in[0];
    const float* valid   = (const float*)d_in[1];
    const float* base    = (const float*)d_in[2];
    const float* Wcu     = (const float*)d_in[3];
    const float* Wcc     = (const float*)d_in[4];
    const float* Wcand_u = (const float*)d_in[5];
    const float* bcand_u = (const float*)d_in[6];
    const float* Wcand_c = (const float*)d_in[7];
    const float* bcand_c = (const float*)d_in[8];
    const float* Wg      = (const float*)d_in[9];
    const float* bg      = (const float*)d_in[10];
    const float* lnug    = (const float*)d_in[11];
    const float* lnub    = (const float*)d_in[12];
    const float* lncg    = (const float*)d_in[13];
    const float* lncb    = (const float*)d_in[14];
    float* out = (float*)d_out;

    k1_lnu<<<BT, 256>>>(u, lnug, lnub);
    k2_lu <<<BT, 256>>>(Wcu);
    k3_rec<<<Bdim, 256>>>(Wcc, valid, lncg, lncb);
    k4_gemm<<<dim3(MC / 128, BT / 128), 256>>>(Wcand_u, Wcand_c, bcand_u, bcand_c);
    k5_dinit<<<Cdim, 128>>>(base);
    for (int t = 0; t < Tdim; t++)
        k_step<<<dim3(NTILE, Bdim), 256>>>(t, t & 1, u, valid, Wg, bg);
    k_out<<<(BT * Mdim) / 256, 256>>>(out);
}

// round 4
// speedup vs baseline: 1.4791x; 1.4791x over previous
#include <cuda_runtime.h>
#include <cuda_bf16.h>
#include <cstdint>

#define Mdim 512
#define Cdim 256
#define Bdim 8
#define Tdim 32
#define BT 256            // B*T
#define MC 131072         // M*C
#define TOPKK 8
#define LAMf 0.05f
#define RHOf 0.9f
#define DLRf 0.03f
#define EPSF 1e-12f
#define LN_EPSF 1e-5f
#define AP 776            // padded A row pitch (floats)
#define NTILE 32          // C / 8 column tiles
#define CPT 8             // columns per tile
#define CPITCH 520        // smem cand pitch

// ---------------- scratch (device globals; no allocation allowed) ----------
__device__ float g_LNu[BT * Mdim];
__device__ float g_A[BT * AP];                     // [u(512) | c_t(256)] rows
__device__ float g_Lu[BT * Cdim];
__device__ float g_ct[BT * Cdim];
__device__ int   g_aidx[BT * TOPKK];
__device__ float g_aval[BT * TOPKK];
__device__ float g_cand[(size_t)BT * MC];          // 128 MiB cand scratch
__device__ float g_D[2][Bdim * Cdim * Mdim];       // ping-pong dictionary [b][c][m]
__device__ float g_zpart[(size_t)BT * NTILE * Mdim];
__device__ unsigned g_bar[Bdim];                   // per-batch step barriers
__device__ uint4 g_Abf_hi4[BT * 768 * 2 / 16];     // A hi bf16 (16B-aligned)
__device__ uint4 g_Abf_lo4[BT * 768 * 2 / 16];     // A lo bf16

// ---------------- helpers --------------------------------------------------
__device__ __forceinline__ uint32_t smem_u32(const void* p) {
    uint32_t a;
    asm("{ .reg .u64 t; cvta.to.shared.u64 t, %1; cvt.u32.u64 %0, t; }" : "=r"(a) : "l"(p));
    return a;
}
__device__ __forceinline__ void ldsm_x4(uint32_t* r, uint32_t addr) {
    asm volatile("ldmatrix.sync.aligned.m8n8.x4.shared.b16 {%0,%1,%2,%3}, [%4];"
        : "=r"(r[0]), "=r"(r[1]), "=r"(r[2]), "=r"(r[3]) : "r"(addr));
}
__device__ __forceinline__ void mma_bf16(float* c, const uint32_t* a, uint32_t b0, uint32_t b1) {
    asm volatile("mma.sync.aligned.m16n8k16.row.col.f32.bf16.bf16.f32 "
        "{%0,%1,%2,%3}, {%4,%5,%6,%7}, {%8,%9}, {%0,%1,%2,%3};"
        : "+f"(c[0]), "+f"(c[1]), "+f"(c[2]), "+f"(c[3])
        : "r"(a[0]), "r"(a[1]), "r"(a[2]), "r"(a[3]), "r"(b0), "r"(b1));
}
__device__ __forceinline__ float blockReduceSum(float v, float* sh) {
    __syncthreads();
    #pragma unroll
    for (int o = 16; o; o >>= 1) v += __shfl_xor_sync(0xffffffffu, v, o);
    int w = threadIdx.x >> 5, l = threadIdx.x & 31;
    if (l == 0) sh[w] = v;
    __syncthreads();
    if (w == 0) {
        float x = (l < (int)(blockDim.x >> 5)) ? sh[l] : 0.f;
        #pragma unroll
        for (int o = 4; o; o >>= 1) x += __shfl_xor_sync(0xffffffffu, x, o);
        if (l == 0) sh[0] = x;
    }
    __syncthreads();
    return sh[0];
}

// ---------------- K1: LN(u), fill A u-part ---------------------------------
__global__ void k1_lnu(const float* __restrict__ u,
                       const float* __restrict__ g, const float* __restrict__ bb) {
    __shared__ float sh[8];
    int r = blockIdx.x, tid = threadIdx.x;
    const float* ur = u + (size_t)r * Mdim;
    float x0 = ur[tid], x1 = ur[tid + 256];
    float s = blockReduceSum(x0 + x1, sh);
    float mu = s * (1.f / Mdim);
    float d0 = x0 - mu, d1 = x1 - mu;
    float var = blockReduceSum(d0 * d0 + d1 * d1, sh) * (1.f / Mdim);
    float inv = rsqrtf(var + LN_EPSF);
    g_LNu[(size_t)r * Mdim + tid]       = d0 * inv * g[tid] + bb[tid];
    g_LNu[(size_t)r * Mdim + tid + 256] = d1 * inv * g[tid + 256] + bb[tid + 256];
    g_A[(size_t)r * AP + tid]       = x0;
    g_A[(size_t)r * AP + tid + 256] = x1;
}

// ---------------- K2: Lu = LN(u) @ W_cu^T ---------------------------------
__global__ void k2_lu(const float* __restrict__ Wcu) {
    __shared__ float ln[Mdim];
    int r = blockIdx.x, c = threadIdx.x;
    ln[c]       = g_LNu[(size_t)r * Mdim + c];
    ln[c + 256] = g_LNu[(size_t)r * Mdim + c + 256];
    __syncthreads();
    const float4* wr = (const float4*)(Wcu + (size_t)c * Mdim);
    float acc = 0.f;
    #pragma unroll 8
    for (int i = 0; i < 128; i++) {
        float4 w = wr[i];
        acc += w.x * ln[4*i] + w.y * ln[4*i+1] + w.z * ln[4*i+2] + w.w * ln[4*i+3];
    }
    g_Lu[r * Cdim + c] = acc;
}

// ---------------- K3: sequential sparse-code recurrence --------------------
__global__ void k3_rec(const float* __restrict__ Wcc, const float* __restrict__ valid,
                       const float* __restrict__ lncg, const float* __restrict__ lncb) {
    __shared__ float sh[8];
    __shared__ float cprev[Cdim], lnc[Cdim], sarr[Cdim], sval[Cdim], aD[Cdim];
    __shared__ float wv[8];
    __shared__ int   wi[8];
    int b = blockIdx.x, c = threadIdx.x;
    cprev[c] = 0.f;
    __syncthreads();
    for (int t = 0; t < Tdim; t++) {
        int bt = b * Tdim + t;
        float cp = cprev[c];
        float s  = blockReduceSum(cp, sh);
        float mu = s * (1.f / Cdim);
        float d  = cp - mu;
        float var = blockReduceSum(d * d, sh) * (1.f / Cdim);
        lnc[c] = d * rsqrtf(var + LN_EPSF) * lncg[c] + lncb[c];
        __syncthreads();
        const float4* wr = (const float4*)(Wcc + (size_t)c * Cdim);
        float acc = g_Lu[bt * Cdim + c];
        #pragma unroll 8
        for (int i = 0; i < 64; i++) {
            float4 w = wr[i];
            acc += w.x * lnc[4*i] + w.y * lnc[4*i+1] + w.z * lnc[4*i+2] + w.w * lnc[4*i+3];
        }
        float aa  = fabsf(acc) - LAMf;
        float shr = aa > 0.f ? copysignf(aa, acc) : 0.f;
        sarr[c] = shr; sval[c] = fabsf(shr); aD[c] = 0.f;
        __syncthreads();
        for (int k = 0; k < TOPKK; k++) {
            float v = sval[c]; int idx = c;
            #pragma unroll
            for (int o = 16; o; o >>= 1) {
                float ov = __shfl_xor_sync(0xffffffffu, v, o);
                int   oi = __shfl_xor_sync(0xffffffffu, idx, o);
                if (ov > v || (ov == v && oi < idx)) { v = ov; idx = oi; }
            }
            int w = c >> 5;
            if ((c & 31) == 0) { wv[w] = v; wi[w] = idx; }
            __syncthreads();
            if (c == 0) {
                float bv = wv[0]; int bi = wi[0];
                #pragma unroll
                for (int j = 1; j < 8; j++)
                    if (wv[j] > bv || (wv[j] == bv && wi[j] < bi)) { bv = wv[j]; bi = wi[j]; }
                aD[bi] = sarr[bi];
                g_aidx[bt * TOPKK + k] = bi;
                g_aval[bt * TOPKK + k] = sarr[bi];
                sval[bi] = -1.f;
            }
            __syncthreads();
        }
        float v  = valid[bt];
        float cn = RHOf * cp + (1.f - RHOf) * aD[c];
        float ct = v * cn + (1.f - v) * cp;
        g_ct[bt * Cdim + c] = ct;
        g_A[(size_t)bt * AP + Mdim + c] = ct;
        cprev[c] = ct;
        __syncthreads();
    }
}

// ---------------- K3b: pre-split A rows into bf16 hi/lo --------------------
__global__ void k_acvt() {
    int r = blockIdx.x, tid = threadIdx.x;
    __nv_bfloat16* ph = (__nv_bfloat16*)g_Abf_hi4;
    __nv_bfloat16* pl = (__nv_bfloat16*)g_Abf_lo4;
    for (int j = tid; j < 768; j += 256) {
        float v = g_A[(size_t)r * AP + j];
        __nv_bfloat16 h = __float2bfloat16_rn(v);
        ph[r * 768 + j] = h;
        pl[r * 768 + j] = __float2bfloat16_rn(v - __bfloat162float(h));
    }
}

// ---------------- K4: cand GEMM via mma.sync bf16x3 split ------------------
// Block: 256 bt rows x 64 weight cols, K = 768. Warps 4(m) x 2(n), 64x32 each.
#define SOFF_A_HI 0
#define SOFF_A_LO 20480
#define SOFF_W_HI 40960
#define SOFF_W_LO 46080
#define SOFF_BIAS 51200
#define K4_SMEM   51456
#define APITCH 80   // bytes per smem A/W row (32 bf16 + 8 pad)

__global__ void __launch_bounds__(256, 2)
k4_mma(const float* __restrict__ Wu, const float* __restrict__ Wc,
       const float* __restrict__ bu, const float* __restrict__ bc) {
    extern __shared__ char sm[];
    uint32_t sb = smem_u32(sm);
    int tid = threadIdx.x, wid = tid >> 5, lane = tid & 31;
    int wm = wid & 3, wn = wid >> 2;
    int n0 = blockIdx.x * 64;

    if (tid < 64) ((float*)(sm + SOFF_BIAS))[tid] = bu[n0 + tid] + bc[n0 + tid];

    float acc[4][4][4];
    #pragma unroll
    for (int i = 0; i < 4; i++)
        #pragma unroll
        for (int j = 0; j < 4; j++)
            #pragma unroll
            for (int k = 0; k < 4; k++) acc[i][j][k] = 0.f;

    // ldmatrix per-lane offsets (non-trans fragments for both A and B)
    uint32_t aoff[4], boff[2];
    #pragma unroll
    for (int mt = 0; mt < 4; mt++)
        aoff[mt] = (uint32_t)((wm * 64 + mt * 16 + (lane & 15)) * APITCH + (lane >> 4) * 16);
    #pragma unroll
    for (int np = 0; np < 2; np++)
        boff[np] = (uint32_t)((wn * 32 + np * 16 + (lane & 7) + ((lane >> 4) << 3)) * APITCH
                              + ((lane >> 3) & 1) * 16);

    const __nv_bfloat16* Ah = (const __nv_bfloat16*)g_Abf_hi4;
    const __nv_bfloat16* Al = (const __nv_bfloat16*)g_Abf_lo4;

    for (int q = 0; q < 24; q++) {
        int k0 = q * 32;
        const float* Wp; int sw;
        if (k0 < 512) { Wp = Wu + k0; sw = 512; } else { Wp = Wc + (k0 - 512); sw = 256; }
        __syncthreads();
        // stage W (convert fp32 -> hi/lo bf16): 64 rows x 32 cols
        #pragma unroll
        for (int i = 0; i < 2; i++) {
            int s = tid + i * 256;
            int row = s >> 3, c4 = (s & 7) * 4;
            float4 v = *(const float4*)(Wp + (size_t)(n0 + row) * sw + c4);
            __nv_bfloat16 h0 = __float2bfloat16_rn(v.x), h1 = __float2bfloat16_rn(v.y);
            __nv_bfloat16 h2 = __float2bfloat16_rn(v.z), h3 = __float2bfloat16_rn(v.w);
            uint2 hi, lo;
            hi.x = (uint32_t)__bfloat16_as_ushort(h0) | ((uint32_t)__bfloat16_as_ushort(h1) << 16);
            hi.y = (uint32_t)__bfloat16_as_ushort(h2) | ((uint32_t)__bfloat16_as_ushort(h3) << 16);
            __nv_bfloat16 l0 = __float2bfloat16_rn(v.x - __bfloat162float(h0));
            __nv_bfloat16 l1 = __float2bfloat16_rn(v.y - __bfloat162float(h1));
            __nv_bfloat16 l2 = __float2bfloat16_rn(v.z - __bfloat162float(h2));
            __nv_bfloat16 l3 = __float2bfloat16_rn(v.w - __bfloat162float(h3));
            lo.x = (uint32_t)__bfloat16_as_ushort(l0) | ((uint32_t)__bfloat16_as_ushort(l1) << 16);
            lo.y = (uint32_t)__bfloat16_as_ushort(l2) | ((uint32_t)__bfloat16_as_ushort(l3) << 16);
            *(uint2*)(sm + SOFF_W_HI + row * APITCH + c4 * 2) = hi;
            *(uint2*)(sm + SOFF_W_LO + row * APITCH + c4 * 2) = lo;
        }
        // stage A (bf16 copy): 256 rows x 32 cols, hi & lo
        #pragma unroll
        for (int i = 0; i < 4; i++) {
            int s = tid + i * 256;
            int row = s >> 2, qq = s & 3;
            *(uint4*)(sm + SOFF_A_HI + row * APITCH + qq * 16) =
                *(const uint4*)(Ah + (size_t)row * 768 + k0 + qq * 8);
            *(uint4*)(sm + SOFF_A_LO + row * APITCH + qq * 16) =
                *(const uint4*)(Al + (size_t)row * 768 + k0 + qq * 8);
        }
        __syncthreads();
        #pragma unroll
        for (int kh = 0; kh < 2; kh++) {
            uint32_t ah[4][4], al[4][4], bh[2][4], bl[2][4];
            #pragma unroll
            for (int mt = 0; mt < 4; mt++) {
                ldsm_x4(ah[mt], sb + SOFF_A_HI + aoff[mt] + kh * 32);
                ldsm_x4(al[mt], sb + SOFF_A_LO + aoff[mt] + kh * 32);
            }
            #pragma unroll
            for (int np = 0; np < 2; np++) {
                ldsm_x4(bh[np], sb + SOFF_W_HI + boff[np] + kh * 32);
                ldsm_x4(bl[np], sb + SOFF_W_LO + boff[np] + kh * 32);
            }
            #pragma unroll
            for (int mt = 0; mt < 4; mt++)
                #pragma unroll
                for (int nf = 0; nf < 4; nf++) {
                    int np = nf >> 1, hh = (nf & 1) * 2;
                    mma_bf16(acc[mt][nf], ah[mt], bh[np][hh], bh[np][hh + 1]);
                    mma_bf16(acc[mt][nf], ah[mt], bl[np][hh], bl[np][hh + 1]);
                    mma_bf16(acc[mt][nf], al[mt], bh[np][hh], bh[np][hh + 1]);
                }
        }
    }
    // epilogue
    const float* bias = (const float*)(sm + SOFF_BIAS);
    #pragma unroll
    for (int mt = 0; mt < 4; mt++) {
        int row = wm * 64 + mt * 16 + (lane >> 2);
        #pragma unroll
        for (int nf = 0; nf < 4; nf++) {
            int cl = wn * 32 + nf * 8 + (lane & 3) * 2;
            float b0 = bias[cl], b1 = bias[cl + 1];
            float2 v0 = make_float2(acc[mt][nf][0] + b0, acc[mt][nf][1] + b1);
            float2 v1 = make_float2(acc[mt][nf][2] + b0, acc[mt][nf][3] + b1);
            *(float2*)(g_cand + (size_t)row * MC + n0 + cl)       = v0;
            *(float2*)(g_cand + (size_t)(row + 8) * MC + n0 + cl) = v1;
        }
    }
}

// ---------------- K5: D0 init + barrier reset ------------------------------
__global__ void k5_dinit(const float* __restrict__ base) {
    __shared__ float sh[8];
    int c = blockIdx.x, tid = threadIdx.x;  // 128 threads
    if (c < Bdim && tid == 0) g_bar[c] = 0;
    float s = 0.f;
    for (int m = tid; m < Mdim; m += 128) {
        float v = base[(size_t)m * Cdim + c];
        s += v * v;
    }
    float stot = blockReduceSum(s, sh);
    float inv = 1.f / fmaxf(sqrtf(stot), EPSF);
    for (int b = 0; b < Bdim; b++)
        for (int m = tid; m < Mdim; m += 128)
            g_D[0][((size_t)b * Cdim + c) * Mdim + m] = base[(size_t)m * Cdim + c] * inv;
}

// ---------------- K6: persistent dictionary-update steps -------------------
__global__ void __launch_bounds__(256, 2)
k_steps(const float* __restrict__ u, const float* __restrict__ valid,
        const float* __restrict__ Wg, const float* __restrict__ bg) {
    __shared__ float sh[8];
    __shared__ float rsh[Mdim];
    __shared__ float ctsh[Cdim];
    __shared__ float cnd[CPT][CPITCH];
    __shared__ int   aidx[TOPKK];
    __shared__ float aval[TOPKK];
    __shared__ float gsh;
    int tile = blockIdx.x, b = blockIdx.y, tid = threadIdx.x;
    int c0 = tile * CPT;
    int w = tid >> 5, lane = tid & 31;
    int cc = c0 + w;

    for (int t = 0; t < Tdim; t++) {
        int sbuf = t & 1;
        const float* Dsrc = g_D[sbuf];
        float*       Ddst = g_D[sbuf ^ 1];
        int bt = b * Tdim + t;
        const float* ur = u + (size_t)bt * Mdim;
        float vv = valid[bt];
        ctsh[tid] = g_ct[bt * Cdim + tid];
        if (tid < TOPKK) { aidx[tid] = g_aidx[bt * TOPKK + tid]; aval[tid] = g_aval[bt * TOPKK + tid]; }
        __syncthreads();
        float perr = 0.f, pg = 0.f;
        #pragma unroll
        for (int h = 0; h < 2; h++) {
            int m = tid + h * 256;
            float acc = ur[m];
            #pragma unroll
            for (int j = 0; j < TOPKK; j++)
                acc -= Dsrc[((size_t)b * Cdim + aidx[j]) * Mdim + m] * aval[j];
            rsh[m] = acc;
            perr += acc * acc;
            pg   += Wg[m] * ur[m];
        }
        pg += Wg[Mdim + tid] * ctsh[tid];
        const float* cb = g_cand + (size_t)bt * MC + c0;
        for (int i = tid; i < Mdim * CPT; i += 256) {
            int mm = i >> 3, j = i & 7;
            cnd[j][mm] = cb[(size_t)mm * Cdim + j];
        }
        float errsum = blockReduceSum(perr, sh);
        float gsum   = blockReduceSum(pg, sh);
        if (tid == 0) {
            float err = sqrtf(errsum);
            float gp  = gsum + Wg[Mdim + Cdim] * err + bg[0];
            gsh = 1.f / (1.f + expf(-gp));
        }
        __syncthreads();
        float g = gsh;
        float av = 0.f;
        #pragma unroll
        for (int j = 0; j < TOPKK; j++)
            if (aidx[j] == cc) av = aval[j];
        const float* Dc = Dsrc + ((size_t)b * Cdim + cc) * Mdim;
        float*       Do = Ddst + ((size_t)b * Cdim + cc) * Mdim;
        float Dreg[16];
        float sl = 0.f, sc2 = 0.f, sx = 0.f;
        float dla = DLRf * av;
        #pragma unroll
        for (int k = 0; k < 16; k++) {
            int m = lane + 32 * k;
            float dd = Dc[m]; Dreg[k] = dd;
            float dl = fmaf(dla, rsh[m], dd);
            float cn = cnd[w][m];
            sl  = fmaf(dl, dl, sl);
            sc2 = fmaf(cn, cn, sc2);
            sx  = fmaf(dl, cn, sx);
        }
        #pragma unroll
        for (int o = 16; o; o >>= 1) {
            sl  += __shfl_xor_sync(0xffffffffu, sl,  o);
            sc2 += __shfl_xor_sync(0xffffffffu, sc2, o);
            sx  += __shfl_xor_sync(0xffffffffu, sx,  o);
        }
        float il  = 1.f / fmaxf(sqrtf(sl),  EPSF);
        float icn = 1.f / fmaxf(sqrtf(sc2), EPSF);
        float w1 = (1.f - g) * il, w2 = g * icn;
        float smix = w1 * w1 * sl + 2.f * w1 * w2 * sx + w2 * w2 * sc2;
        float imix = 1.f / fmaxf(sqrtf(smix), EPSF);
        float ctc = ctsh[cc];
        #pragma unroll
        for (int k = 0; k < 16; k++) {
            int m = lane + 32 * k;
            float dl  = fmaf(dla, rsh[m], Dreg[k]);
            float cn  = cnd[w][m];
            float mix = w1 * dl + w2 * cn;
            float dn  = vv * (mix * imix) + (1.f - vv) * Dreg[k];
            Do[m] = dn;
            cnd[w][m] = dn * ctc;
        }
        __syncthreads();
        float* zp = g_zpart + ((size_t)bt * NTILE + tile) * Mdim;
        for (int m = tid; m < Mdim; m += 256) {
            float z = 0.f;
            #pragma unroll
            for (int j = 0; j < CPT; j++) z += cnd[j][m];
            zp[m] = z;
        }
        // inter-step barrier (32 blocks of this batch)
        __threadfence();
        __syncthreads();
        if (tid == 0) atomicAdd(&g_bar[b], 1u);
        if (t + 1 < Tdim) {
            if (tid == 0) {
                unsigned tgt = (unsigned)((t + 1) * NTILE);
                while (atomicAdd(&g_bar[b], 0u) < tgt) __nanosleep(64);
            }
            __syncthreads();
            __threadfence();
        }
    }
}

// ---------------- K7: reduce z partials -> output --------------------------
__global__ void k_out(float* __restrict__ out) {
    int gi = blockIdx.x * 256 + threadIdx.x;   // < BT * M
    int bt = gi >> 9, m = gi & 511;
    const float* zp = g_zpart + (size_t)bt * NTILE * Mdim + m;
    float s = 0.f;
    #pragma unroll
    for (int j = 0; j < NTILE; j++) s += zp[(size_t)j * Mdim];
    out[gi] = s;
}

// ---------------- launch ---------------------------------------------------
extern "C" void kernel_launch(void* const* d_in, const int* in_sizes, int n_in,
                              void* d_out, int out_size) {
    const float* u       = (const float*)d_in[0];
    const float* valid   = (const float*)d_in[1];
    const float* base    = (const float*)d_in[2];
    const float* Wcu     = (const float*)d_in[3];
    const float* Wcc     = (const float*)d_in[4];
    const float* Wcand_u = (const float*)d_in[5];
    const float* bcand_u = (const float*)d_in[6];
    const float* Wcand_c = (const float*)d_in[7];
    const float* bcand_c = (const float*)d_in[8];
    const float* Wg      = (const float*)d_in[9];
    const float* bg      = (const float*)d_in[10];
    const float* lnug    = (const float*)d_in[11];
    const float* lnub    = (const float*)d_in[12];
    const float* lncg    = (const float*)d_in[13];
    const float* lncb    = (const float*)d_in[14];
    float* out = (float*)d_out;

    cudaFuncSetAttribute(k4_mma, cudaFuncAttributeMaxDynamicSharedMemorySize, K4_SMEM);

    k1_lnu<<<BT, 256>>>(u, lnug, lnub);
    k2_lu <<<BT, 256>>>(Wcu);
    k3_rec<<<Bdim, 256>>>(Wcc, valid, lncg, lncb);
    k_acvt<<<BT, 256>>>();
    k4_mma<<<MC / 64, 256, K4_SMEM>>>(Wcand_u, Wcand_c, bcand_u, bcand_c);
    k5_dinit<<<Cdim, 128>>>(base);
    k_steps<<<dim3(NTILE, Bdim), 256>>>(u, valid, Wg, bg);
    k_out<<<(BT * Mdim) / 256, 256>>>(out);
}

// round 5
// speedup vs baseline: 1.5883x; 1.0738x over previous
#include <cuda_runtime.h>
#include <cuda_bf16.h>
#include <cstdint>

#define Mdim 512
#define Cdim 256
#define Bdim 8
#define Tdim 32
#define BT 256            // B*T
#define MC 131072         // M*C
#define TOPKK 8
#define LAMf 0.05f
#define RHOf 0.9f
#define DLRf 0.03f
#define EPSF 1e-12f
#define LN_EPSF 1e-5f
#define AP 776            // padded A row pitch (floats)
#define NTILE 32          // C / 8 column tiles
#define CPT 8             // columns per tile
#define CPITCH 520        // smem cand pitch

// ---------------- scratch (device globals; no allocation allowed) ----------
__device__ float g_LNu[BT * Mdim];
__device__ float g_A[BT * AP];                     // [u(512) | c_t(256)] rows
__device__ float g_Lu[BT * Cdim];
__device__ float g_ct[BT * Cdim];
__device__ int   g_aidx[BT * TOPKK];
__device__ float g_aval[BT * TOPKK];
__device__ float g_cand[(size_t)BT * MC];          // 128 MiB cand scratch
__device__ float g_D[2][Bdim * Cdim * Mdim];       // ping-pong dictionary [b][c][m]
__device__ float g_zpart[(size_t)BT * NTILE * Mdim];
__device__ unsigned g_bar[Bdim];                   // per-batch step barriers
__device__ uint4 g_Abf_hi4[BT * 768 * 2 / 16];     // A hi bf16 (16B-aligned)
__device__ uint4 g_Abf_lo4[BT * 768 * 2 / 16];     // A lo bf16

// ---------------- helpers --------------------------------------------------
__device__ __forceinline__ uint32_t smem_u32(const void* p) {
    uint32_t a;
    asm("{ .reg .u64 t; cvta.to.shared.u64 t, %1; cvt.u32.u64 %0, t; }" : "=r"(a) : "l"(p));
    return a;
}
__device__ __forceinline__ void ldsm_x4(uint32_t* r, uint32_t addr) {
    asm volatile("ldmatrix.sync.aligned.m8n8.x4.shared.b16 {%0,%1,%2,%3}, [%4];"
        : "=r"(r[0]), "=r"(r[1]), "=r"(r[2]), "=r"(r[3]) : "r"(addr));
}
__device__ __forceinline__ void mma_bf16(float* c, const uint32_t* a, uint32_t b0, uint32_t b1) {
    asm volatile("mma.sync.aligned.m16n8k16.row.col.f32.bf16.bf16.f32 "
        "{%0,%1,%2,%3}, {%4,%5,%6,%7}, {%8,%9}, {%0,%1,%2,%3};"
        : "+f"(c[0]), "+f"(c[1]), "+f"(c[2]), "+f"(c[3])
        : "r"(a[0]), "r"(a[1]), "r"(a[2]), "r"(a[3]), "r"(b0), "r"(b1));
}
__device__ __forceinline__ void cpasync16(uint32_t dst, const void* src) {
    asm volatile("cp.async.cg.shared.global [%0], [%1], 16;" :: "r"(dst), "l"(src));
}
__device__ __forceinline__ float blockReduceSum(float v, float* sh) {
    __syncthreads();
    #pragma unroll
    for (int o = 16; o; o >>= 1) v += __shfl_xor_sync(0xffffffffu, v, o);
    int w = threadIdx.x >> 5, l = threadIdx.x & 31;
    if (l == 0) sh[w] = v;
    __syncthreads();
    if (w == 0) {
        float x = (l < (int)(blockDim.x >> 5)) ? sh[l] : 0.f;
        #pragma unroll
        for (int o = 4; o; o >>= 1) x += __shfl_xor_sync(0xffffffffu, x, o);
        if (l == 0) sh[0] = x;
    }
    __syncthreads();
    return sh[0];
}

// ---------------- K1: LN(u), fill A u-part ---------------------------------
__global__ void k1_lnu(const float* __restrict__ u,
                       const float* __restrict__ g, const float* __restrict__ bb) {
    __shared__ float sh[8];
    int r = blockIdx.x, tid = threadIdx.x;
    const float* ur = u + (size_t)r * Mdim;
    float x0 = ur[tid], x1 = ur[tid + 256];
    float s = blockReduceSum(x0 + x1, sh);
    float mu = s * (1.f / Mdim);
    float d0 = x0 - mu, d1 = x1 - mu;
    float var = blockReduceSum(d0 * d0 + d1 * d1, sh) * (1.f / Mdim);
    float inv = rsqrtf(var + LN_EPSF);
    g_LNu[(size_t)r * Mdim + tid]       = d0 * inv * g[tid] + bb[tid];
    g_LNu[(size_t)r * Mdim + tid + 256] = d1 * inv * g[tid + 256] + bb[tid + 256];
    g_A[(size_t)r * AP + tid]       = x0;
    g_A[(size_t)r * AP + tid + 256] = x1;
}

// ---------------- K2: Lu = LN(u) @ W_cu^T ---------------------------------
__global__ void k2_lu(const float* __restrict__ Wcu) {
    __shared__ float ln[Mdim];
    int r = blockIdx.x, c = threadIdx.x;
    ln[c]       = g_LNu[(size_t)r * Mdim + c];
    ln[c + 256] = g_LNu[(size_t)r * Mdim + c + 256];
    __syncthreads();
    const float4* wr = (const float4*)(Wcu + (size_t)c * Mdim);
    float acc = 0.f;
    #pragma unroll 8
    for (int i = 0; i < 128; i++) {
        float4 w = wr[i];
        acc += w.x * ln[4*i] + w.y * ln[4*i+1] + w.z * ln[4*i+2] + w.w * ln[4*i+3];
    }
    g_Lu[r * Cdim + c] = acc;
}

// ---------------- K3: sequential sparse-code recurrence --------------------
__global__ void k3_rec(const float* __restrict__ Wcc, const float* __restrict__ valid,
                       const float* __restrict__ lncg, const float* __restrict__ lncb) {
    __shared__ float sh[8];
    __shared__ float cprev[Cdim], lnc[Cdim], sarr[Cdim], sval[Cdim], aD[Cdim];
    __shared__ float wv[8];
    __shared__ int   wi[8];
    int b = blockIdx.x, c = threadIdx.x;
    cprev[c] = 0.f;
    __syncthreads();
    for (int t = 0; t < Tdim; t++) {
        int bt = b * Tdim + t;
        float cp = cprev[c];
        float s  = blockReduceSum(cp, sh);
        float mu = s * (1.f / Cdim);
        float d  = cp - mu;
        float var = blockReduceSum(d * d, sh) * (1.f / Cdim);
        lnc[c] = d * rsqrtf(var + LN_EPSF) * lncg[c] + lncb[c];
        __syncthreads();
        const float4* wr = (const float4*)(Wcc + (size_t)c * Cdim);
        float acc = g_Lu[bt * Cdim + c];
        #pragma unroll 8
        for (int i = 0; i < 64; i++) {
            float4 w = wr[i];
            acc += w.x * lnc[4*i] + w.y * lnc[4*i+1] + w.z * lnc[4*i+2] + w.w * lnc[4*i+3];
        }
        float aa  = fabsf(acc) - LAMf;
        float shr = aa > 0.f ? copysignf(aa, acc) : 0.f;
        sarr[c] = shr; sval[c] = fabsf(shr); aD[c] = 0.f;
        __syncthreads();
        for (int k = 0; k < TOPKK; k++) {
            float v = sval[c]; int idx = c;
            #pragma unroll
            for (int o = 16; o; o >>= 1) {
                float ov = __shfl_xor_sync(0xffffffffu, v, o);
                int   oi = __shfl_xor_sync(0xffffffffu, idx, o);
                if (ov > v || (ov == v && oi < idx)) { v = ov; idx = oi; }
            }
            int w = c >> 5;
            if ((c & 31) == 0) { wv[w] = v; wi[w] = idx; }
            __syncthreads();
            if (c == 0) {
                float bv = wv[0]; int bi = wi[0];
                #pragma unroll
                for (int j = 1; j < 8; j++)
                    if (wv[j] > bv || (wv[j] == bv && wi[j] < bi)) { bv = wv[j]; bi = wi[j]; }
                aD[bi] = sarr[bi];
                g_aidx[bt * TOPKK + k] = bi;
                g_aval[bt * TOPKK + k] = sarr[bi];
                sval[bi] = -1.f;
            }
            __syncthreads();
        }
        float v  = valid[bt];
        float cn = RHOf * cp + (1.f - RHOf) * aD[c];
        float ct = v * cn + (1.f - v) * cp;
        g_ct[bt * Cdim + c] = ct;
        g_A[(size_t)bt * AP + Mdim + c] = ct;
        cprev[c] = ct;
        __syncthreads();
    }
}

// ---------------- K3b: pre-split A rows into bf16 hi/lo --------------------
__global__ void k_acvt() {
    int r = blockIdx.x, tid = threadIdx.x;
    __nv_bfloat16* ph = (__nv_bfloat16*)g_Abf_hi4;
    __nv_bfloat16* pl = (__nv_bfloat16*)g_Abf_lo4;
    for (int j = tid; j < 768; j += 256) {
        float v = g_A[(size_t)r * AP + j];
        __nv_bfloat16 h = __float2bfloat16_rn(v);
        ph[r * 768 + j] = h;
        pl[r * 768 + j] = __float2bfloat16_rn(v - __bfloat162float(h));
    }
}

// ---------------- K4: pipelined cand GEMM (mma.sync bf16x3) ----------------
// Block: 256 bt rows x 64 weight cols, K = 768. Warps 4(m) x 2(n), 64x32 each.
// A double-buffered via cp.async; W register-prefetched one K-tile ahead.
#define SOFF_A 0            // 4 x 20480: hi0, lo0, hi1, lo1
#define SOFF_W_HI 81920
#define SOFF_W_LO 87040
#define SOFF_BIAS 92160
#define K4_SMEM   92416
#define APITCH 80   // bytes per smem A/W row (32 bf16 + 8 pad)

__device__ __forceinline__ void stage_A(uint32_t sb, int buf, int k0, int tid) {
    uint32_t hbase = sb + SOFF_A + buf * 40960;
    uint32_t lbase = hbase + 20480;
    #pragma unroll
    for (int i = 0; i < 4; i++) {
        int s = tid + i * 256;
        int row = s >> 2, qq = s & 3;
        size_t soff = ((size_t)row * 768 + k0) * 2 + qq * 16;
        cpasync16(hbase + row * APITCH + qq * 16, (const char*)g_Abf_hi4 + soff);
        cpasync16(lbase + row * APITCH + qq * 16, (const char*)g_Abf_lo4 + soff);
    }
}
__device__ __forceinline__ void ldW(const float* __restrict__ Wu, const float* __restrict__ Wc,
                                    int n0, int q, int tid, float4* w) {
    int k0 = q * 32; const float* Wp; int sw;
    if (k0 < 512) { Wp = Wu + k0; sw = 512; } else { Wp = Wc + (k0 - 512); sw = 256; }
    #pragma unroll
    for (int i = 0; i < 2; i++) {
        int s = tid + i * 256;
        int row = s >> 3, c4 = (s & 7) * 4;
        w[i] = *(const float4*)(Wp + (size_t)(n0 + row) * sw + c4);
    }
}

__global__ void __launch_bounds__(256, 2)
k4_mma(const float* __restrict__ Wu, const float* __restrict__ Wc,
       const float* __restrict__ bu, const float* __restrict__ bc) {
    extern __shared__ char sm[];
    uint32_t sb = smem_u32(sm);
    int tid = threadIdx.x, wid = tid >> 5, lane = tid & 31;
    int wm = wid & 3, wn = wid >> 2;
    int n0 = blockIdx.x * 64;

    if (tid < 64) ((float*)(sm + SOFF_BIAS))[tid] = bu[n0 + tid] + bc[n0 + tid];

    float acc[4][4][4];
    #pragma unroll
    for (int i = 0; i < 4; i++)
        #pragma unroll
        for (int j = 0; j < 4; j++)
            #pragma unroll
            for (int k = 0; k < 4; k++) acc[i][j][k] = 0.f;

    // ldmatrix per-lane offsets (non-trans fragments for both A and B)
    uint32_t aoff[4], boff[2];
    #pragma unroll
    for (int mt = 0; mt < 4; mt++)
        aoff[mt] = (uint32_t)((wm * 64 + mt * 16 + (lane & 15)) * APITCH + (lane >> 4) * 16);
    #pragma unroll
    for (int np = 0; np < 2; np++)
        boff[np] = (uint32_t)((wn * 32 + np * 16 + (lane & 7) + ((lane >> 4) << 3)) * APITCH
                              + ((lane >> 3) & 1) * 16);

    // prologue: stage A(0), prefetch W(0)
    stage_A(sb, 0, 0, tid);
    asm volatile("cp.async.commit_group;" ::: "memory");
    float4 wreg[2];
    ldW(Wu, Wc, n0, 0, tid, wreg);

    for (int q = 0; q < 24; q++) {
        int buf = q & 1;
        __syncthreads();   // all warps done with Wsm and A[buf^1] from previous iter
        // store W(q) (convert fp32 -> hi/lo bf16)
        #pragma unroll
        for (int i = 0; i < 2; i++) {
            int s = tid + i * 256;
            int row = s >> 3, c4 = (s & 7) * 4;
            float4 v = wreg[i];
            __nv_bfloat16 h0 = __float2bfloat16_rn(v.x), h1 = __float2bfloat16_rn(v.y);
            __nv_bfloat16 h2 = __float2bfloat16_rn(v.z), h3 = __float2bfloat16_rn(v.w);
            uint2 hi, lo;
            hi.x = (uint32_t)__bfloat16_as_ushort(h0) | ((uint32_t)__bfloat16_as_ushort(h1) << 16);
            hi.y = (uint32_t)__bfloat16_as_ushort(h2) | ((uint32_t)__bfloat16_as_ushort(h3) << 16);
            __nv_bfloat16 l0 = __float2bfloat16_rn(v.x - __bfloat162float(h0));
            __nv_bfloat16 l1 = __float2bfloat16_rn(v.y - __bfloat162float(h1));
            __nv_bfloat16 l2 = __float2bfloat16_rn(v.z - __bfloat162float(h2));
            __nv_bfloat16 l3 = __float2bfloat16_rn(v.w - __bfloat162float(h3));
            lo.x = (uint32_t)__bfloat16_as_ushort(l0) | ((uint32_t)__bfloat16_as_ushort(l1) << 16);
            lo.y = (uint32_t)__bfloat16_as_ushort(l2) | ((uint32_t)__bfloat16_as_ushort(l3) << 16);
            *(uint2*)(sm + SOFF_W_HI + row * APITCH + c4 * 2) = hi;
            *(uint2*)(sm + SOFF_W_LO + row * APITCH + c4 * 2) = lo;
        }
        if (q + 1 < 24) {
            stage_A(sb, buf ^ 1, (q + 1) * 32, tid);       // A(q+1) in flight during compute
            asm volatile("cp.async.commit_group;" ::: "memory");
            ldW(Wu, Wc, n0, q + 1, tid, wreg);             // W(q+1) in flight during compute
            asm volatile("cp.async.wait_group 1;" ::: "memory");
        } else {
            asm volatile("cp.async.wait_group 0;" ::: "memory");
        }
        __syncthreads();
        // compute on A[buf] + Wsm
        uint32_t abh = sb + SOFF_A + buf * 40960;
        uint32_t abl = abh + 20480;
        #pragma unroll
        for (int kh = 0; kh < 2; kh++) {
            uint32_t ah[4][4], al[4][4];
            #pragma unroll
            for (int mt = 0; mt < 4; mt++) {
                ldsm_x4(ah[mt], abh + aoff[mt] + kh * 32);
                ldsm_x4(al[mt], abl + aoff[mt] + kh * 32);
            }
            #pragma unroll
            for (int np = 0; np < 2; np++) {
                uint32_t bh[4], bl[4];
                ldsm_x4(bh, sb + SOFF_W_HI + boff[np] + kh * 32);
                ldsm_x4(bl, sb + SOFF_W_LO + boff[np] + kh * 32);
                #pragma unroll
                for (int h = 0; h < 2; h++) {
                    #pragma unroll
                    for (int mt = 0; mt < 4; mt++)
                        mma_bf16(acc[mt][np * 2 + h], ah[mt], bh[h * 2], bh[h * 2 + 1]);
                    #pragma unroll
                    for (int mt = 0; mt < 4; mt++)
                        mma_bf16(acc[mt][np * 2 + h], ah[mt], bl[h * 2], bl[h * 2 + 1]);
                    #pragma unroll
                    for (int mt = 0; mt < 4; mt++)
                        mma_bf16(acc[mt][np * 2 + h], al[mt], bh[h * 2], bh[h * 2 + 1]);
                }
            }
        }
    }
    // epilogue
    const float* bias = (const float*)(sm + SOFF_BIAS);
    #pragma unroll
    for (int mt = 0; mt < 4; mt++) {
        int row = wm * 64 + mt * 16 + (lane >> 2);
        #pragma unroll
        for (int nf = 0; nf < 4; nf++) {
            int cl = wn * 32 + nf * 8 + (lane & 3) * 2;
            float b0 = bias[cl], b1 = bias[cl + 1];
            float2 v0 = make_float2(acc[mt][nf][0] + b0, acc[mt][nf][1] + b1);
            float2 v1 = make_float2(acc[mt][nf][2] + b0, acc[mt][nf][3] + b1);
            *(float2*)(g_cand + (size_t)row * MC + n0 + cl)       = v0;
            *(float2*)(g_cand + (size_t)(row + 8) * MC + n0 + cl) = v1;
        }
    }
}

// ---------------- K5: D0 init + barrier reset ------------------------------
__global__ void k5_dinit(const float* __restrict__ base) {
    __shared__ float sh[8];
    int c = blockIdx.x, tid = threadIdx.x;  // 128 threads
    if (c < Bdim && tid == 0) g_bar[c] = 0;
    float s = 0.f;
    for (int m = tid; m < Mdim; m += 128) {
        float v = base[(size_t)m * Cdim + c];
        s += v * v;
    }
    float stot = blockReduceSum(s, sh);
    float inv = 1.f / fmaxf(sqrtf(stot), EPSF);
    for (int b = 0; b < Bdim; b++)
        for (int m = tid; m < Mdim; m += 128)
            g_D[0][((size_t)b * Cdim + c) * Mdim + m] = base[(size_t)m * Cdim + c] * inv;
}

// ---------------- K6: persistent dictionary-update steps -------------------
__global__ void __launch_bounds__(256, 2)
k_steps(const float* __restrict__ u, const float* __restrict__ valid,
        const float* __restrict__ Wg, const float* __restrict__ bg) {
    __shared__ float sh[8];
    __shared__ float rsh[Mdim];
    __shared__ float ctsh[Cdim];
    __shared__ float cnd[CPT][CPITCH];
    __shared__ int   aidx[TOPKK];
    __shared__ float aval[TOPKK];
    __shared__ float gsh;
    int tile = blockIdx.x, b = blockIdx.y, tid = threadIdx.x;
    int c0 = tile * CPT;
    int w = tid >> 5, lane = tid & 31;
    int cc = c0 + w;

    for (int t = 0; t < Tdim; t++) {
        int sbuf = t & 1;
        const float* Dsrc = g_D[sbuf];
        float*       Ddst = g_D[sbuf ^ 1];
        int bt = b * Tdim + t;
        const float* ur = u + (size_t)bt * Mdim;
        float vv = valid[bt];
        ctsh[tid] = g_ct[bt * Cdim + tid];
        if (tid < TOPKK) { aidx[tid] = g_aidx[bt * TOPKK + tid]; aval[tid] = g_aval[bt * TOPKK + tid]; }
        __syncthreads();
        float perr = 0.f, pg = 0.f;
        #pragma unroll
        for (int h = 0; h < 2; h++) {
            int m = tid + h * 256;
            float acc = ur[m];
            #pragma unroll
            for (int j = 0; j < TOPKK; j++)
                acc -= Dsrc[((size_t)b * Cdim + aidx[j]) * Mdim + m] * aval[j];
            rsh[m] = acc;
            perr += acc * acc;
            pg   += Wg[m] * ur[m];
        }
        pg += Wg[Mdim + tid] * ctsh[tid];
        const float* cb = g_cand + (size_t)bt * MC + c0;
        for (int i = tid; i < Mdim * CPT; i += 256) {
            int mm = i >> 3, j = i & 7;
            cnd[j][mm] = cb[(size_t)mm * Cdim + j];
        }
        float errsum = blockReduceSum(perr, sh);
        float gsum   = blockReduceSum(pg, sh);
        if (tid == 0) {
            float err = sqrtf(errsum);
            float gp  = gsum + Wg[Mdim + Cdim] * err + bg[0];
            gsh = 1.f / (1.f + expf(-gp));
        }
        __syncthreads();
        float g = gsh;
        float av = 0.f;
        #pragma unroll
        for (int j = 0; j < TOPKK; j++)
            if (aidx[j] == cc) av = aval[j];
        const float* Dc = Dsrc + ((size_t)b * Cdim + cc) * Mdim;
        float*       Do = Ddst + ((size_t)b * Cdim + cc) * Mdim;
        float Dreg[16];
        float sl = 0.f, sc2 = 0.f, sx = 0.f;
        float dla = DLRf * av;
        #pragma unroll
        for (int k = 0; k < 16; k++) {
            int m = lane + 32 * k;
            float dd = Dc[m]; Dreg[k] = dd;
            float dl = fmaf(dla, rsh[m], dd);
            float cn = cnd[w][m];
            sl  = fmaf(dl, dl, sl);
            sc2 = fmaf(cn, cn, sc2);
            sx  = fmaf(dl, cn, sx);
        }
        #pragma unroll
        for (int o = 16; o; o >>= 1) {
            sl  += __shfl_xor_sync(0xffffffffu, sl,  o);
            sc2 += __shfl_xor_sync(0xffffffffu, sc2, o);
            sx  += __shfl_xor_sync(0xffffffffu, sx,  o);
        }
        float il  = 1.f / fmaxf(sqrtf(sl),  EPSF);
        float icn = 1.f / fmaxf(sqrtf(sc2), EPSF);
        float w1 = (1.f - g) * il, w2 = g * icn;
        float smix = w1 * w1 * sl + 2.f * w1 * w2 * sx + w2 * w2 * sc2;
        float imix = 1.f / fmaxf(sqrtf(smix), EPSF);
        float ctc = ctsh[cc];
        #pragma unroll
        for (int k = 0; k < 16; k++) {
            int m = lane + 32 * k;
            float dl  = fmaf(dla, rsh[m], Dreg[k]);
            float cn  = cnd[w][m];
            float mix = w1 * dl + w2 * cn;
            float dn  = vv * (mix * imix) + (1.f - vv) * Dreg[k];
            Do[m] = dn;
            cnd[w][m] = dn * ctc;
        }
        __syncthreads();
        float* zp = g_zpart + ((size_t)bt * NTILE + tile) * Mdim;
        for (int m = tid; m < Mdim; m += 256) {
            float z = 0.f;
            #pragma unroll
            for (int j = 0; j < CPT; j++) z += cnd[j][m];
            zp[m] = z;
        }
        // inter-step barrier (32 blocks of this batch)
        __threadfence();
        __syncthreads();
        if (tid == 0) atomicAdd(&g_bar[b], 1u);
        if (t + 1 < Tdim) {
            if (tid == 0) {
                unsigned tgt = (unsigned)((t + 1) * NTILE);
                while (atomicAdd(&g_bar[b], 0u) < tgt) __nanosleep(32);
            }
            __syncthreads();
            __threadfence();
        }
    }
}

// ---------------- K7: reduce z partials -> output --------------------------
__global__ void k_out(float* __restrict__ out) {
    int gi = blockIdx.x * 256 + threadIdx.x;   // < BT * M
    int bt = gi >> 9, m = gi & 511;
    const float* zp = g_zpart + (size_t)bt * NTILE * Mdim + m;
    float s = 0.f;
    #pragma unroll
    for (int j = 0; j < NTILE; j++) s += zp[(size_t)j * Mdim];
    out[gi] = s;
}

// ---------------- launch ---------------------------------------------------
extern "C" void kernel_launch(void* const* d_in, const int* in_sizes, int n_in,
                              void* d_out, int out_size) {
    const float* u       = (const float*)d_in[0];
    const float* valid   = (const float*)d_in[1];
    const float* base    = (const float*)d_in[2];
    const float* Wcu     = (const float*)d_in[3];
    const float* Wcc     = (const float*)d_in[4];
    const float* Wcand_u = (const float*)d_in[5];
    const float* bcand_u = (const float*)d_in[6];
    const float* Wcand_c = (const float*)d_in[7];
    const float* bcand_c = (const float*)d_in[8];
    const float* Wg      = (const float*)d_in[9];
    const float* bg      = (const float*)d_in[10];
    const float* lnug    = (const float*)d_in[11];
    const float* lnub    = (const float*)d_in[12];
    const float* lncg    = (const float*)d_in[13];
    const float* lncb    = (const float*)d_in[14];
    float* out = (float*)d_out;

    cudaFuncSetAttribute(k4_mma, cudaFuncAttributeMaxDynamicSharedMemorySize, K4_SMEM);

    k5_dinit<<<Cdim, 128>>>(base);
    k1_lnu<<<BT, 256>>>(u, lnug, lnub);
    k2_lu <<<BT, 256>>>(Wcu);
    k3_rec<<<Bdim, 256>>>(Wcc, valid, lncg, lncb);
    k_acvt<<<BT, 256>>>();
    k4_mma<<<MC / 64, 256, K4_SMEM>>>(Wcand_u, Wcand_c, bcand_u, bcand_c);
    k_steps<<<dim3(NTILE, Bdim), 256>>>(u, valid, Wg, bg);
    k_out<<<(BT * Mdim) / 256, 256>>>(out);
}

// round 6
// speedup vs baseline: 1.6137x; 1.0160x over previous
#include <cuda_runtime.h>
#include <cuda_bf16.h>
#include <cstdint>

#define Mdim 512
#define Cdim 256
#define Bdim 8
#define Tdim 32
#define BT 256            // B*T
#define MC 131072         // M*C
#define TOPKK 8
#define LAMf 0.05f
#define RHOf 0.9f
#define DLRf 0.03f
#define EPSF 1e-12f
#define LN_EPSF 1e-5f
#define AP 776            // padded A row pitch (floats)
#define NTILE 32          // C / 8 column tiles
#define CPT 8             // columns per tile
#define CPITCH 520        // smem cand pitch

// ---------------- scratch (device globals; no allocation allowed) ----------
__device__ float g_LNu[BT * Mdim];
__device__ float g_A[BT * AP];                     // [u(512) | c_t(256)] rows
__device__ float g_Lu[BT * Cdim];
__device__ float g_ct[BT * Cdim];
__device__ int   g_aidx[BT * TOPKK];
__device__ float g_aval[BT * TOPKK];
__device__ float g_cand[(size_t)BT * MC];          // 128 MiB cand scratch
__device__ float g_D[2][Bdim * Cdim * Mdim];       // ping-pong dictionary [b][c][m]
__device__ float g_zpart[(size_t)BT * NTILE * Mdim];
__device__ unsigned g_bar[Bdim];                   // per-batch step barriers
__device__ uint4 g_Abf_hi4[BT * 768 * 2 / 16];     // A hi bf16 (16B-aligned)
__device__ uint4 g_Abf_lo4[BT * 768 * 2 / 16];     // A lo bf16

// ---------------- helpers --------------------------------------------------
__device__ __forceinline__ uint32_t smem_u32(const void* p) {
    uint32_t a;
    asm("{ .reg .u64 t; cvta.to.shared.u64 t, %1; cvt.u32.u64 %0, t; }" : "=r"(a) : "l"(p));
    return a;
}
__device__ __forceinline__ void ldsm_x4(uint32_t* r, uint32_t addr) {
    asm volatile("ldmatrix.sync.aligned.m8n8.x4.shared.b16 {%0,%1,%2,%3}, [%4];"
        : "=r"(r[0]), "=r"(r[1]), "=r"(r[2]), "=r"(r[3]) : "r"(addr));
}
__device__ __forceinline__ void mma_bf16(float* c, const uint32_t* a, uint32_t b0, uint32_t b1) {
    asm volatile("mma.sync.aligned.m16n8k16.row.col.f32.bf16.bf16.f32 "
        "{%0,%1,%2,%3}, {%4,%5,%6,%7}, {%8,%9}, {%0,%1,%2,%3};"
        : "+f"(c[0]), "+f"(c[1]), "+f"(c[2]), "+f"(c[3])
        : "r"(a[0]), "r"(a[1]), "r"(a[2]), "r"(a[3]), "r"(b0), "r"(b1));
}
__device__ __forceinline__ void cpasync16(uint32_t dst, const void* src) {
    asm volatile("cp.async.cg.shared.global [%0], [%1], 16;" :: "r"(dst), "l"(src));
}
__device__ __forceinline__ float blockReduceSum(float v, float* sh) {
    __syncthreads();
    #pragma unroll
    for (int o = 16; o; o >>= 1) v += __shfl_xor_sync(0xffffffffu, v, o);
    int w = threadIdx.x >> 5, l = threadIdx.x & 31;
    if (l == 0) sh[w] = v;
    __syncthreads();
    if (w == 0) {
        float x = (l < (int)(blockDim.x >> 5)) ? sh[l] : 0.f;
        #pragma unroll
        for (int o = 4; o; o >>= 1) x += __shfl_xor_sync(0xffffffffu, x, o);
        if (l == 0) sh[0] = x;
    }
    __syncthreads();
    return sh[0];
}

// ---------------- K1: LN(u), fill A u-part ---------------------------------
__global__ void k1_lnu(const float* __restrict__ u,
                       const float* __restrict__ g, const float* __restrict__ bb) {
    __shared__ float sh[8];
    int r = blockIdx.x, tid = threadIdx.x;
    const float* ur = u + (size_t)r * Mdim;
    float x0 = ur[tid], x1 = ur[tid + 256];
    float s = blockReduceSum(x0 + x1, sh);
    float mu = s * (1.f / Mdim);
    float d0 = x0 - mu, d1 = x1 - mu;
    float var = blockReduceSum(d0 * d0 + d1 * d1, sh) * (1.f / Mdim);
    float inv = rsqrtf(var + LN_EPSF);
    g_LNu[(size_t)r * Mdim + tid]       = d0 * inv * g[tid] + bb[tid];
    g_LNu[(size_t)r * Mdim + tid + 256] = d1 * inv * g[tid + 256] + bb[tid + 256];
    g_A[(size_t)r * AP + tid]       = x0;
    g_A[(size_t)r * AP + tid + 256] = x1;
}

// ---------------- K2: Lu = LN(u) @ W_cu^T ---------------------------------
__global__ void k2_lu(const float* __restrict__ Wcu) {
    __shared__ float ln[Mdim];
    int r = blockIdx.x, c = threadIdx.x;
    ln[c]       = g_LNu[(size_t)r * Mdim + c];
    ln[c + 256] = g_LNu[(size_t)r * Mdim + c + 256];
    __syncthreads();
    const float4* wr = (const float4*)(Wcu + (size_t)c * Mdim);
    float a0 = 0.f, a1 = 0.f, a2 = 0.f, a3 = 0.f;
    #pragma unroll 4
    for (int i = 0; i < 128; i += 4) {
        float4 w0 = wr[i],   w1 = wr[i+1], w2 = wr[i+2], w3 = wr[i+3];
        a0 = fmaf(w0.x, ln[4*i+0], fmaf(w0.y, ln[4*i+1], fmaf(w0.z, ln[4*i+2], fmaf(w0.w, ln[4*i+3], a0))));
        a1 = fmaf(w1.x, ln[4*i+4], fmaf(w1.y, ln[4*i+5], fmaf(w1.z, ln[4*i+6], fmaf(w1.w, ln[4*i+7], a1))));
        a2 = fmaf(w2.x, ln[4*i+8], fmaf(w2.y, ln[4*i+9], fmaf(w2.z, ln[4*i+10], fmaf(w2.w, ln[4*i+11], a2))));
        a3 = fmaf(w3.x, ln[4*i+12], fmaf(w3.y, ln[4*i+13], fmaf(w3.z, ln[4*i+14], fmaf(w3.w, ln[4*i+15], a3))));
    }
    g_Lu[r * Cdim + c] = (a0 + a1) + (a2 + a3);
}

// ---------------- K3: sequential sparse-code recurrence (optimized) --------
// One block per batch. c_prev register-resident; fused (sum,sumsq) LN reduce;
// 4-acc GEMV; two-level shuffle top-8 (warp-local then warp-0 merge).
__global__ void __launch_bounds__(256, 1)
k3_rec(const float* __restrict__ Wcc, const float* __restrict__ valid,
       const float* __restrict__ lncg, const float* __restrict__ lncb) {
    __shared__ float sh[16];          // [0:8) sum partials, [8:16) sumsq partials
    __shared__ float lnc[Cdim];
    __shared__ float shr_sm[Cdim];
    __shared__ float cwv[64];
    __shared__ int   cwi[64];
    __shared__ float t8v[TOPKK];
    __shared__ int   t8i[TOPKK];
    int b = blockIdx.x, c = threadIdx.x;
    int w = c >> 5, lane = c & 31;
    float cp = 0.f;
    float gC = lncg[c], bC = lncb[c];
    const float4* wr = (const float4*)(Wcc + (size_t)c * Cdim);

    for (int t = 0; t < Tdim; t++) {
        int bt = b * Tdim + t;
        // ---- fused LN reduction: (sum, sumsq) in one pass ----
        float s1 = cp, s2 = cp * cp;
        #pragma unroll
        for (int o = 16; o; o >>= 1) {
            s1 += __shfl_xor_sync(0xffffffffu, s1, o);
            s2 += __shfl_xor_sync(0xffffffffu, s2, o);
        }
        if (lane == 0) { sh[w] = s1; sh[8 + w] = s2; }
        __syncthreads();
        float t1 = 0.f, t2 = 0.f;
        #pragma unroll
        for (int j = 0; j < 8; j++) { t1 += sh[j]; t2 += sh[8 + j]; }
        float mu  = t1 * (1.f / Cdim);
        float var = t2 * (1.f / Cdim) - mu * mu;
        float inv = rsqrtf(var + LN_EPSF);
        lnc[c] = (cp - mu) * inv * gC + bC;
        __syncthreads();
        // ---- GEMV: acc = Lu + Wcc[c,:] . lnc  (4 accumulators) ----
        const float4* lv = (const float4*)lnc;
        float a0 = g_Lu[bt * Cdim + c], a1 = 0.f, a2 = 0.f, a3 = 0.f;
        #pragma unroll 4
        for (int i = 0; i < 64; i += 4) {
            float4 w0 = wr[i],   l0 = lv[i];
            float4 w1 = wr[i+1], l1 = lv[i+1];
            float4 w2 = wr[i+2], l2 = lv[i+2];
            float4 w3 = wr[i+3], l3 = lv[i+3];
            a0 = fmaf(w0.x, l0.x, fmaf(w0.y, l0.y, fmaf(w0.z, l0.z, fmaf(w0.w, l0.w, a0))));
            a1 = fmaf(w1.x, l1.x, fmaf(w1.y, l1.y, fmaf(w1.z, l1.z, fmaf(w1.w, l1.w, a1))));
            a2 = fmaf(w2.x, l2.x, fmaf(w2.y, l2.y, fmaf(w2.z, l2.z, fmaf(w2.w, l2.w, a2))));
            a3 = fmaf(w3.x, l3.x, fmaf(w3.y, l3.y, fmaf(w3.z, l3.z, fmaf(w3.w, l3.w, a3))));
        }
        float acc = (a0 + a1) + (a2 + a3);
        // ---- shrink ----
        float aa  = fabsf(acc) - LAMf;
        float shr = aa > 0.f ? copysignf(aa, acc) : 0.f;
        shr_sm[c] = shr;
        // ---- warp-local top-8 (shuffle argmax, tie -> lowest index) ----
        float myv = fabsf(shr); int myi = c;
        #pragma unroll
        for (int k = 0; k < TOPKK; k++) {
            float mv = myv; int mi = myi;
            #pragma unroll
            for (int o = 16; o; o >>= 1) {
                float ov = __shfl_xor_sync(0xffffffffu, mv, o);
                int   oi = __shfl_xor_sync(0xffffffffu, mi, o);
                if (ov > mv || (ov == mv && oi < mi)) { mv = ov; mi = oi; }
            }
            if (lane == 0) { cwv[w * 8 + k] = mv; cwi[w * 8 + k] = mi; }
            if (myi == mi) myv = -1.f;
        }
        __syncthreads();
        // ---- warp-0 merge of 64 candidates -> global top-8 ----
        if (w == 0) {
            float v0 = cwv[lane], v1 = cwv[32 + lane];
            int   i0 = cwi[lane], i1 = cwi[32 + lane];
            #pragma unroll
            for (int k = 0; k < TOPKK; k++) {
                float bv; int bi;
                if (v0 > v1 || (v0 == v1 && i0 < i1)) { bv = v0; bi = i0; }
                else                                   { bv = v1; bi = i1; }
                #pragma unroll
                for (int o = 16; o; o >>= 1) {
                    float ov = __shfl_xor_sync(0xffffffffu, bv, o);
                    int   oi = __shfl_xor_sync(0xffffffffu, bi, o);
                    if (ov > bv || (ov == bv && oi < bi)) { bv = ov; bi = oi; }
                }
                if (lane == 0) {
                    float sv = shr_sm[bi];
                    t8v[k] = sv; t8i[k] = bi;
                    g_aidx[bt * TOPKK + k] = bi;
                    g_aval[bt * TOPKK + k] = sv;
                }
                if (i0 == bi) v0 = -1.f;
                if (i1 == bi) v1 = -1.f;
            }
        }
        __syncthreads();
        // ---- c update (register-carried) ----
        float ac = 0.f;
        #pragma unroll
        for (int j = 0; j < TOPKK; j++)
            if (t8i[j] == c) ac = t8v[j];
        float vv = valid[bt];
        float cn = RHOf * cp + (1.f - RHOf) * ac;
        cp = vv * cn + (1.f - vv) * cp;
        g_ct[bt * Cdim + c] = cp;
        g_A[(size_t)bt * AP + Mdim + c] = cp;
    }
}

// ---------------- K3b: pre-split A rows into bf16 hi/lo --------------------
__global__ void k_acvt() {
    int r = blockIdx.x, tid = threadIdx.x;
    __nv_bfloat16* ph = (__nv_bfloat16*)g_Abf_hi4;
    __nv_bfloat16* pl = (__nv_bfloat16*)g_Abf_lo4;
    for (int j = tid; j < 768; j += 256) {
        float v = g_A[(size_t)r * AP + j];
        __nv_bfloat16 h = __float2bfloat16_rn(v);
        ph[r * 768 + j] = h;
        pl[r * 768 + j] = __float2bfloat16_rn(v - __bfloat162float(h));
    }
}

// ---------------- K4: pipelined cand GEMM (mma.sync bf16x3) ----------------
#define SOFF_A 0            // 4 x 20480: hi0, lo0, hi1, lo1
#define SOFF_W_HI 81920
#define SOFF_W_LO 87040
#define SOFF_BIAS 92160
#define K4_SMEM   92416
#define APITCH 80   // bytes per smem A/W row (32 bf16 + 8 pad)

__device__ __forceinline__ void stage_A(uint32_t sb, int buf, int k0, int tid) {
    uint32_t hbase = sb + SOFF_A + buf * 40960;
    uint32_t lbase = hbase + 20480;
    #pragma unroll
    for (int i = 0; i < 4; i++) {
        int s = tid + i * 256;
        int row = s >> 2, qq = s & 3;
        size_t soff = ((size_t)row * 768 + k0) * 2 + qq * 16;
        cpasync16(hbase + row * APITCH + qq * 16, (const char*)g_Abf_hi4 + soff);
        cpasync16(lbase + row * APITCH + qq * 16, (const char*)g_Abf_lo4 + soff);
    }
}
__device__ __forceinline__ void ldW(const float* __restrict__ Wu, const float* __restrict__ Wc,
                                    int n0, int q, int tid, float4* w) {
    int k0 = q * 32; const float* Wp; int sw;
    if (k0 < 512) { Wp = Wu + k0; sw = 512; } else { Wp = Wc + (k0 - 512); sw = 256; }
    #pragma unroll
    for (int i = 0; i < 2; i++) {
        int s = tid + i * 256;
        int row = s >> 3, c4 = (s & 7) * 4;
        w[i] = *(const float4*)(Wp + (size_t)(n0 + row) * sw + c4);
    }
}

__global__ void __launch_bounds__(256, 2)
k4_mma(const float* __restrict__ Wu, const float* __restrict__ Wc,
       const float* __restrict__ bu, const float* __restrict__ bc) {
    extern __shared__ char sm[];
    uint32_t sb = smem_u32(sm);
    int tid = threadIdx.x, wid = tid >> 5, lane = tid & 31;
    int wm = wid & 3, wn = wid >> 2;
    int n0 = blockIdx.x * 64;

    if (tid < 64) ((float*)(sm + SOFF_BIAS))[tid] = bu[n0 + tid] + bc[n0 + tid];

    float acc[4][4][4];
    #pragma unroll
    for (int i = 0; i < 4; i++)
        #pragma unroll
        for (int j = 0; j < 4; j++)
            #pragma unroll
            for (int k = 0; k < 4; k++) acc[i][j][k] = 0.f;

    uint32_t aoff[4], boff[2];
    #pragma unroll
    for (int mt = 0; mt < 4; mt++)
        aoff[mt] = (uint32_t)((wm * 64 + mt * 16 + (lane & 15)) * APITCH + (lane >> 4) * 16);
    #pragma unroll
    for (int np = 0; np < 2; np++)
        boff[np] = (uint32_t)((wn * 32 + np * 16 + (lane & 7) + ((lane >> 4) << 3)) * APITCH
                              + ((lane >> 3) & 1) * 16);

    stage_A(sb, 0, 0, tid);
    asm volatile("cp.async.commit_group;" ::: "memory");
    float4 wreg[2];
    ldW(Wu, Wc, n0, 0, tid, wreg);

    for (int q = 0; q < 24; q++) {
        int buf = q & 1;
        __syncthreads();
        #pragma unroll
        for (int i = 0; i < 2; i++) {
            int s = tid + i * 256;
            int row = s >> 3, c4 = (s & 7) * 4;
            float4 v = wreg[i];
            __nv_bfloat16 h0 = __float2bfloat16_rn(v.x), h1 = __float2bfloat16_rn(v.y);
            __nv_bfloat16 h2 = __float2bfloat16_rn(v.z), h3 = __float2bfloat16_rn(v.w);
            uint2 hi, lo;
            hi.x = (uint32_t)__bfloat16_as_ushort(h0) | ((uint32_t)__bfloat16_as_ushort(h1) << 16);
            hi.y = (uint32_t)__bfloat16_as_ushort(h2) | ((uint32_t)__bfloat16_as_ushort(h3) << 16);
            __nv_bfloat16 l0 = __float2bfloat16_rn(v.x - __bfloat162float(h0));
            __nv_bfloat16 l1 = __float2bfloat16_rn(v.y - __bfloat162float(h1));
            __nv_bfloat16 l2 = __float2bfloat16_rn(v.z - __bfloat162float(h2));
            __nv_bfloat16 l3 = __float2bfloat16_rn(v.w - __bfloat162float(h3));
            lo.x = (uint32_t)__bfloat16_as_ushort(l0) | ((uint32_t)__bfloat16_as_ushort(l1) << 16);
            lo.y = (uint32_t)__bfloat16_as_ushort(l2) | ((uint32_t)__bfloat16_as_ushort(l3) << 16);
            *(uint2*)(sm + SOFF_W_HI + row * APITCH + c4 * 2) = hi;
            *(uint2*)(sm + SOFF_W_LO + row * APITCH + c4 * 2) = lo;
        }
        if (q + 1 < 24) {
            stage_A(sb, buf ^ 1, (q + 1) * 32, tid);
            asm volatile("cp.async.commit_group;" ::: "memory");
            ldW(Wu, Wc, n0, q + 1, tid, wreg);
            asm volatile("cp.async.wait_group 1;" ::: "memory");
        } else {
            asm volatile("cp.async.wait_group 0;" ::: "memory");
        }
        __syncthreads();
        uint32_t abh = sb + SOFF_A + buf * 40960;
        uint32_t abl = abh + 20480;
        #pragma unroll
        for (int kh = 0; kh < 2; kh++) {
            uint32_t ah[4][4], al[4][4];
            #pragma unroll
            for (int mt = 0; mt < 4; mt++) {
                ldsm_x4(ah[mt], abh + aoff[mt] + kh * 32);
                ldsm_x4(al[mt], abl + aoff[mt] + kh * 32);
            }
            #pragma unroll
            for (int np = 0; np < 2; np++) {
                uint32_t bh[4], bl[4];
                ldsm_x4(bh, sb + SOFF_W_HI + boff[np] + kh * 32);
                ldsm_x4(bl, sb + SOFF_W_LO + boff[np] + kh * 32);
                #pragma unroll
                for (int h = 0; h < 2; h++) {
                    #pragma unroll
                    for (int mt = 0; mt < 4; mt++)
                        mma_bf16(acc[mt][np * 2 + h], ah[mt], bh[h * 2], bh[h * 2 + 1]);
                    #pragma unroll
                    for (int mt = 0; mt < 4; mt++)
                        mma_bf16(acc[mt][np * 2 + h], ah[mt], bl[h * 2], bl[h * 2 + 1]);
                    #pragma unroll
                    for (int mt = 0; mt < 4; mt++)
                        mma_bf16(acc[mt][np * 2 + h], al[mt], bh[h * 2], bh[h * 2 + 1]);
                }
            }
        }
    }
    const float* bias = (const float*)(sm + SOFF_BIAS);
    #pragma unroll
    for (int mt = 0; mt < 4; mt++) {
        int row = wm * 64 + mt * 16 + (lane >> 2);
        #pragma unroll
        for (int nf = 0; nf < 4; nf++) {
            int cl = wn * 32 + nf * 8 + (lane & 3) * 2;
            float b0 = bias[cl], b1 = bias[cl + 1];
            float2 v0 = make_float2(acc[mt][nf][0] + b0, acc[mt][nf][1] + b1);
            float2 v1 = make_float2(acc[mt][nf][2] + b0, acc[mt][nf][3] + b1);
            *(float2*)(g_cand + (size_t)row * MC + n0 + cl)       = v0;
            *(float2*)(g_cand + (size_t)(row + 8) * MC + n0 + cl) = v1;
        }
    }
}

// ---------------- K5: D0 init + barrier reset ------------------------------
__global__ void k5_dinit(const float* __restrict__ base) {
    __shared__ float sh[8];
    int c = blockIdx.x, tid = threadIdx.x;  // 128 threads
    if (c < Bdim && tid == 0) g_bar[c] = 0;
    float s = 0.f;
    for (int m = tid; m < Mdim; m += 128) {
        float v = base[(size_t)m * Cdim + c];
        s += v * v;
    }
    float stot = blockReduceSum(s, sh);
    float inv = 1.f / fmaxf(sqrtf(stot), EPSF);
    for (int b = 0; b < Bdim; b++)
        for (int m = tid; m < Mdim; m += 128)
            g_D[0][((size_t)b * Cdim + c) * Mdim + m] = base[(size_t)m * Cdim + c] * inv;
}

// ---------------- K6: persistent dictionary-update steps -------------------
__global__ void __launch_bounds__(256, 2)
k_steps(const float* __restrict__ u, const float* __restrict__ valid,
        const float* __restrict__ Wg, const float* __restrict__ bg) {
    __shared__ float sh[8];
    __shared__ float rsh[Mdim];
    __shared__ float ctsh[Cdim];
    __shared__ float cnd[CPT][CPITCH];
    __shared__ int   aidx[TOPKK];
    __shared__ float aval[TOPKK];
    __shared__ float gsh;
    int tile = blockIdx.x, b = blockIdx.y, tid = threadIdx.x;
    int c0 = tile * CPT;
    int w = tid >> 5, lane = tid & 31;
    int cc = c0 + w;

    for (int t = 0; t < Tdim; t++) {
        int sbuf = t & 1;
        const float* Dsrc = g_D[sbuf];
        float*       Ddst = g_D[sbuf ^ 1];
        int bt = b * Tdim + t;
        const float* ur = u + (size_t)bt * Mdim;
        float vv = valid[bt];
        ctsh[tid] = g_ct[bt * Cdim + tid];
        if (tid < TOPKK) { aidx[tid] = g_aidx[bt * TOPKK + tid]; aval[tid] = g_aval[bt * TOPKK + tid]; }
        __syncthreads();
        float perr = 0.f, pg = 0.f;
        #pragma unroll
        for (int h = 0; h < 2; h++) {
            int m = tid + h * 256;
            float acc = ur[m];
            #pragma unroll
            for (int j = 0; j < TOPKK; j++)
                acc -= Dsrc[((size_t)b * Cdim + aidx[j]) * Mdim + m] * aval[j];
            rsh[m] = acc;
            perr += acc * acc;
            pg   += Wg[m] * ur[m];
        }
        pg += Wg[Mdim + tid] * ctsh[tid];
        const float* cb = g_cand + (size_t)bt * MC + c0;
        for (int i = tid; i < Mdim * CPT; i += 256) {
            int mm = i >> 3, j = i & 7;
            cnd[j][mm] = cb[(size_t)mm * Cdim + j];
        }
        float errsum = blockReduceSum(perr, sh);
        float gsum   = blockReduceSum(pg, sh);
        if (tid == 0) {
            float err = sqrtf(errsum);
            float gp  = gsum + Wg[Mdim + Cdim] * err + bg[0];
            gsh = 1.f / (1.f + expf(-gp));
        }
        __syncthreads();
        float g = gsh;
        float av = 0.f;
        #pragma unroll
        for (int j = 0; j < TOPKK; j++)
            if (aidx[j] == cc) av = aval[j];
        const float* Dc = Dsrc + ((size_t)b * Cdim + cc) * Mdim;
        float*       Do = Ddst + ((size_t)b * Cdim + cc) * Mdim;
        float Dreg[16];
        float sl = 0.f, sc2 = 0.f, sx = 0.f;
        float dla = DLRf * av;
        #pragma unroll
        for (int k = 0; k < 16; k++) {
            int m = lane + 32 * k;
            float dd = Dc[m]; Dreg[k] = dd;
            float dl = fmaf(dla, rsh[m], dd);
            float cn = cnd[w][m];
            sl  = fmaf(dl, dl, sl);
            sc2 = fmaf(cn, cn, sc2);
            sx  = fmaf(dl, cn, sx);
        }
        #pragma unroll
        for (int o = 16; o; o >>= 1) {
            sl  += __shfl_xor_sync(0xffffffffu, sl,  o);
            sc2 += __shfl_xor_sync(0xffffffffu, sc2, o);
            sx  += __shfl_xor_sync(0xffffffffu, sx,  o);
        }
        float il  = 1.f / fmaxf(sqrtf(sl),  EPSF);
        float icn = 1.f / fmaxf(sqrtf(sc2), EPSF);
        float w1 = (1.f - g) * il, w2 = g * icn;
        float smix = w1 * w1 * sl + 2.f * w1 * w2 * sx + w2 * w2 * sc2;
        float imix = 1.f / fmaxf(sqrtf(smix), EPSF);
        float ctc = ctsh[cc];
        #pragma unroll
        for (int k = 0; k < 16; k++) {
            int m = lane + 32 * k;
            float dl  = fmaf(dla, rsh[m], Dreg[k]);
            float cn  = cnd[w][m];
            float mix = w1 * dl + w2 * cn;
            float dn  = vv * (mix * imix) + (1.f - vv) * Dreg[k];
            Do[m] = dn;
            cnd[w][m] = dn * ctc;
        }
        __syncthreads();
        float* zp = g_zpart + ((size_t)bt * NTILE + tile) * Mdim;
        for (int m = tid; m < Mdim; m += 256) {
            float z = 0.f;
            #pragma unroll
            for (int j = 0; j < CPT; j++) z += cnd[j][m];
            zp[m] = z;
        }
        __threadfence();
        __syncthreads();
        if (tid == 0) atomicAdd(&g_bar[b], 1u);
        if (t + 1 < Tdim) {
            if (tid == 0) {
                unsigned tgt = (unsigned)((t + 1) * NTILE);
                while (atomicAdd(&g_bar[b], 0u) < tgt) __nanosleep(32);
            }
            __syncthreads();
            __threadfence();
        }
    }
}

// ---------------- K7: reduce z partials -> output --------------------------
__global__ void k_out(float* __restrict__ out) {
    int gi = blockIdx.x * 256 + threadIdx.x;   // < BT * M
    int bt = gi >> 9, m = gi & 511;
    const float* zp = g_zpart + (size_t)bt * NTILE * Mdim + m;
    float s = 0.f;
    #pragma unroll
    for (int j = 0; j < NTILE; j++) s += zp[(size_t)j * Mdim];
    out[gi] = s;
}

// ---------------- launch ---------------------------------------------------
extern "C" void kernel_launch(void* const* d_in, const int* in_sizes, int n_in,
                              void* d_out, int out_size) {
    const float* u       = (const float*)d_in[0];
    const float* valid   = (const float*)d_in[1];
    const float* base    = (const float*)d_in[2];
    const float* Wcu     = (const float*)d_in[3];
    const float* Wcc     = (const float*)d_in[4];
    const float* Wcand_u = (const float*)d_in[5];
    const float* bcand_u = (const float*)d_in[6];
    const float* Wcand_c = (const float*)d_in[7];
    const float* bcand_c = (const float*)d_in[8];
    const float* Wg      = (const float*)d_in[9];
    const float* bg      = (const float*)d_in[10];
    const float* lnug    = (const float*)d_in[11];
    const float* lnub    = (const float*)d_in[12];
    const float* lncg    = (const float*)d_in[13];
    const float* lncb    = (const float*)d_in[14];
    float* out = (float*)d_out;

    cudaFuncSetAttribute(k4_mma, cudaFuncAttributeMaxDynamicSharedMemorySize, K4_SMEM);

    k5_dinit<<<Cdim, 128>>>(base);
    k1_lnu<<<BT, 256>>>(u, lnug, lnub);
    k2_lu <<<BT, 256>>>(Wcu);
    k3_rec<<<Bdim, 256>>>(Wcc, valid, lncg, lncb);
    k_acvt<<<BT, 256>>>();
    k4_mma<<<MC / 64, 256, K4_SMEM>>>(Wcand_u, Wcand_c, bcand_u, bcand_c);
    k_steps<<<dim3(NTILE, Bdim), 256>>>(u, valid, Wg, bg);
    k_out<<<(BT * Mdim) / 256, 256>>>(out);
}

// round 7
// speedup vs baseline: 1.9064x; 1.1814x over previous
#include <cuda_runtime.h>
#include <cuda_bf16.h>
#include <cstdint>

#define Mdim 512
#define Cdim 256
#define Bdim 8
#define Tdim 32
#define BT 256            // B*T
#define MC 131072         // M*C
#define TOPKK 8
#define LAMf 0.05f
#define RHOf 0.9f
#define DLRf 0.03f
#define EPSF 1e-12f
#define LN_EPSF 1e-5f
#define AP 776            // padded A row pitch (floats)
#define NTILE 32          // C / 8 column tiles
#define CPT 8             // columns per tile
#define CPITCH 520        // smem cand pitch

// ---------------- scratch (device globals; no allocation allowed) ----------
__device__ float g_LNu[BT * Mdim];
__device__ float g_A[BT * AP];                     // [u(512) | c_t(256)] rows
__device__ float g_Lu[BT * Cdim];
__device__ float g_ct[BT * Cdim];
__device__ int   g_aidx[BT * TOPKK];
__device__ float g_aval[BT * TOPKK];
__device__ float g_cand[(size_t)BT * MC];          // 128 MiB cand scratch
__device__ float g_D[2][Bdim * Cdim * Mdim];       // ping-pong dictionary [b][c][m]
__device__ float g_zpart[(size_t)BT * NTILE * Mdim];
__device__ unsigned g_bar[Bdim];                   // per-batch step barriers
__device__ uint4 g_Abf_hi4[BT * 768 * 2 / 16];     // A hi bf16 (16B-aligned)
__device__ uint4 g_Abf_lo4[BT * 768 * 2 / 16];     // A lo bf16

// ---------------- helpers --------------------------------------------------
__device__ __forceinline__ uint32_t smem_u32(const void* p) {
    uint32_t a;
    asm("{ .reg .u64 t; cvta.to.shared.u64 t, %1; cvt.u32.u64 %0, t; }" : "=r"(a) : "l"(p));
    return a;
}
__device__ __forceinline__ void ldsm_x4(uint32_t* r, uint32_t addr) {
    asm volatile("ldmatrix.sync.aligned.m8n8.x4.shared.b16 {%0,%1,%2,%3}, [%4];"
        : "=r"(r[0]), "=r"(r[1]), "=r"(r[2]), "=r"(r[3]) : "r"(addr));
}
__device__ __forceinline__ void mma_bf16(float* c, const uint32_t* a, uint32_t b0, uint32_t b1) {
    asm volatile("mma.sync.aligned.m16n8k16.row.col.f32.bf16.bf16.f32 "
        "{%0,%1,%2,%3}, {%4,%5,%6,%7}, {%8,%9}, {%0,%1,%2,%3};"
        : "+f"(c[0]), "+f"(c[1]), "+f"(c[2]), "+f"(c[3])
        : "r"(a[0]), "r"(a[1]), "r"(a[2]), "r"(a[3]), "r"(b0), "r"(b1));
}
__device__ __forceinline__ void cpasync16(uint32_t dst, const void* src) {
    asm volatile("cp.async.cg.shared.global [%0], [%1], 16;" :: "r"(dst), "l"(src));
}
__device__ __forceinline__ void cpasync8(uint32_t dst, const void* src) {
    asm volatile("cp.async.ca.shared.global [%0], [%1], 8;" :: "r"(dst), "l"(src));
}
__device__ __forceinline__ float blockReduceSum(float v, float* sh) {
    __syncthreads();
    #pragma unroll
    for (int o = 16; o; o >>= 1) v += __shfl_xor_sync(0xffffffffu, v, o);
    int w = threadIdx.x >> 5, l = threadIdx.x & 31;
    if (l == 0) sh[w] = v;
    __syncthreads();
    if (w == 0) {
        float x = (l < (int)(blockDim.x >> 5)) ? sh[l] : 0.f;
        #pragma unroll
        for (int o = 4; o; o >>= 1) x += __shfl_xor_sync(0xffffffffu, x, o);
        if (l == 0) sh[0] = x;
    }
    __syncthreads();
    return sh[0];
}

// ---------------- K1: LN(u), fill A u-part ---------------------------------
__global__ void k1_lnu(const float* __restrict__ u,
                       const float* __restrict__ g, const float* __restrict__ bb) {
    __shared__ float sh[8];
    int r = blockIdx.x, tid = threadIdx.x;
    const float* ur = u + (size_t)r * Mdim;
    float x0 = ur[tid], x1 = ur[tid + 256];
    float s = blockReduceSum(x0 + x1, sh);
    float mu = s * (1.f / Mdim);
    float d0 = x0 - mu, d1 = x1 - mu;
    float var = blockReduceSum(d0 * d0 + d1 * d1, sh) * (1.f / Mdim);
    float inv = rsqrtf(var + LN_EPSF);
    g_LNu[(size_t)r * Mdim + tid]       = d0 * inv * g[tid] + bb[tid];
    g_LNu[(size_t)r * Mdim + tid + 256] = d1 * inv * g[tid + 256] + bb[tid + 256];
    g_A[(size_t)r * AP + tid]       = x0;
    g_A[(size_t)r * AP + tid + 256] = x1;
}

// ---------------- K2: Lu = LN(u) @ W_cu^T ---------------------------------
__global__ void k2_lu(const float* __restrict__ Wcu) {
    __shared__ float ln[Mdim];
    int r = blockIdx.x, c = threadIdx.x;
    ln[c]       = g_LNu[(size_t)r * Mdim + c];
    ln[c + 256] = g_LNu[(size_t)r * Mdim + c + 256];
    __syncthreads();
    const float4* wr = (const float4*)(Wcu + (size_t)c * Mdim);
    float a0 = 0.f, a1 = 0.f, a2 = 0.f, a3 = 0.f;
    #pragma unroll 4
    for (int i = 0; i < 128; i += 4) {
        float4 w0 = wr[i],   w1 = wr[i+1], w2 = wr[i+2], w3 = wr[i+3];
        a0 = fmaf(w0.x, ln[4*i+0], fmaf(w0.y, ln[4*i+1], fmaf(w0.z, ln[4*i+2], fmaf(w0.w, ln[4*i+3], a0))));
        a1 = fmaf(w1.x, ln[4*i+4], fmaf(w1.y, ln[4*i+5], fmaf(w1.z, ln[4*i+6], fmaf(w1.w, ln[4*i+7], a1))));
        a2 = fmaf(w2.x, ln[4*i+8], fmaf(w2.y, ln[4*i+9], fmaf(w2.z, ln[4*i+10], fmaf(w2.w, ln[4*i+11], a2))));
        a3 = fmaf(w3.x, ln[4*i+12], fmaf(w3.y, ln[4*i+13], fmaf(w3.z, ln[4*i+14], fmaf(w3.w, ln[4*i+15], a3))));
    }
    g_Lu[r * Cdim + c] = (a0 + a1) + (a2 + a3);
}

// ---------------- K3: sparse-code recurrence, smem-tiled GEMV --------------
// Wcc streamed through 2 x 64KB smem buffers via cp.async (double-buffered,
// loads overlap compute + topk). XOR float2-swizzle -> conflict-free LDS.
// Tile: 256 rows x 64 k-cols, pitch 64 floats. SW(j,r) = (j&16)|((j^r)&15).
#define K3_TILE 65536
#define K3_SMEM (2 * K3_TILE)

__device__ __forceinline__ void k3_load_tile(uint32_t base, const float* __restrict__ Wcc,
                                             int kt, int tid) {
    int r0 = tid >> 5, j = tid & 31;
    int sw = ((j & 16) | 0) * 0;  // placate compiler
    (void)sw;
    #pragma unroll
    for (int i = 0; i < 32; i++) {
        int row = r0 + 8 * i;
        int jj = (j & 16) | ((j ^ row) & 15);
        cpasync8(base + (uint32_t)(row * 64 + jj * 2) * 4,
                 Wcc + (size_t)row * Cdim + kt + j * 2);
    }
    asm volatile("cp.async.commit_group;" ::: "memory");
}

__global__ void __launch_bounds__(256, 1)
k3_rec(const float* __restrict__ Wcc, const float* __restrict__ valid,
       const float* __restrict__ lncg, const float* __restrict__ lncb) {
    extern __shared__ char k3sm[];
    uint32_t wsb = smem_u32(k3sm);
    __shared__ float sh[16];
    __shared__ float lnc[Cdim];
    __shared__ float shr_sm[Cdim];
    __shared__ float cwv[64];
    __shared__ int   cwi[64];
    __shared__ float t8v[TOPKK];
    __shared__ int   t8i[TOPKK];
    int b = blockIdx.x, c = threadIdx.x;
    int w = c >> 5, lane = c & 31;
    float cp = 0.f;
    float gC = lncg[c], bC = lncb[c];

    // per-thread swizzled row base + per-j lnc indices are compile-time foldable
    uint32_t rowbase = wsb;  // + buf*K3_TILE + c*256B computed per use

    // prologue: tiles 0 (buf0) and 1 (buf1) in flight
    k3_load_tile(wsb, Wcc, 0, c);
    k3_load_tile(wsb + K3_TILE, Wcc, 64, c);

    for (int t = 0; t < Tdim; t++) {
        int bt = b * Tdim + t;
        // ---- fused LN reduction ----
        float s1 = cp, s2 = cp * cp;
        #pragma unroll
        for (int o = 16; o; o >>= 1) {
            s1 += __shfl_xor_sync(0xffffffffu, s1, o);
            s2 += __shfl_xor_sync(0xffffffffu, s2, o);
        }
        if (lane == 0) { sh[w] = s1; sh[8 + w] = s2; }
        __syncthreads();
        float t1 = 0.f, t2 = 0.f;
        #pragma unroll
        for (int j = 0; j < 8; j++) { t1 += sh[j]; t2 += sh[8 + j]; }
        float mu  = t1 * (1.f / Cdim);
        float var = t2 * (1.f / Cdim) - mu * mu;
        float inv = rsqrtf(var + LN_EPSF);
        lnc[c] = (cp - mu) * inv * gC + bC;
        // ---- GEMV over 4 streamed tiles ----
        float acc = g_Lu[bt * Cdim + c];
        #pragma unroll
        for (int tile = 0; tile < 4; tile++) {
            int buf = tile & 1;
            asm volatile("cp.async.wait_group 1;" ::: "memory");
            __syncthreads();           // tile data + lnc visible to all
            const float* wb = (const float*)(k3sm + buf * K3_TILE) + c * 64;
            const float2* lv = (const float2*)(lnc + tile * 64);
            float a0 = 0.f, a1 = 0.f, a2 = 0.f, a3 = 0.f;
            #pragma unroll
            for (int j = 0; j < 32; j += 4) {
                float2 w0 = *(const float2*)(wb + 2 * ((j & 16)     | ((j ^ c) & 15)));
                float2 w1 = *(const float2*)(wb + 2 * (((j+1) & 16) | (((j+1) ^ c) & 15)));
                float2 w2 = *(const float2*)(wb + 2 * (((j+2) & 16) | (((j+2) ^ c) & 15)));
                float2 w3 = *(const float2*)(wb + 2 * (((j+3) & 16) | (((j+3) ^ c) & 15)));
                float2 l0 = lv[j], l1 = lv[j+1], l2 = lv[j+2], l3 = lv[j+3];
                a0 = fmaf(w0.x, l0.x, fmaf(w0.y, l0.y, a0));
                a1 = fmaf(w1.x, l1.x, fmaf(w1.y, l1.y, a1));
                a2 = fmaf(w2.x, l2.x, fmaf(w2.y, l2.y, a2));
                a3 = fmaf(w3.x, l3.x, fmaf(w3.y, l3.y, a3));
            }
            acc += (a0 + a1) + (a2 + a3);
            __syncthreads();           // everyone done reading buf before refill
            // refill this buffer with the tile needed 2 ahead (wraps to next step)
            int nk = ((tile + 2) & 3) * 64;
            k3_load_tile(wsb + buf * K3_TILE, Wcc, nk, c);
        }
        // ---- shrink ----
        float aa  = fabsf(acc) - LAMf;
        float shr = aa > 0.f ? copysignf(aa, acc) : 0.f;
        shr_sm[c] = shr;
        // ---- warp-local top-8 ----
        float myv = fabsf(shr); int myi = c;
        #pragma unroll
        for (int k = 0; k < TOPKK; k++) {
            float mv = myv; int mi = myi;
            #pragma unroll
            for (int o = 16; o; o >>= 1) {
                float ov = __shfl_xor_sync(0xffffffffu, mv, o);
                int   oi = __shfl_xor_sync(0xffffffffu, mi, o);
                if (ov > mv || (ov == mv && oi < mi)) { mv = ov; mi = oi; }
            }
            if (lane == 0) { cwv[w * 8 + k] = mv; cwi[w * 8 + k] = mi; }
            if (myi == mi) myv = -1.f;
        }
        __syncthreads();
        // ---- warp-0 merge -> global top-8 ----
        if (w == 0) {
            float v0 = cwv[lane], v1 = cwv[32 + lane];
            int   i0 = cwi[lane], i1 = cwi[32 + lane];
            #pragma unroll
            for (int k = 0; k < TOPKK; k++) {
                float bv; int bi;
                if (v0 > v1 || (v0 == v1 && i0 < i1)) { bv = v0; bi = i0; }
                else                                   { bv = v1; bi = i1; }
                #pragma unroll
                for (int o = 16; o; o >>= 1) {
                    float ov = __shfl_xor_sync(0xffffffffu, bv, o);
                    int   oi = __shfl_xor_sync(0xffffffffu, bi, o);
                    if (ov > bv || (ov == bv && oi < bi)) { bv = ov; bi = oi; }
                }
                if (lane == 0) {
                    float sv = shr_sm[bi];
                    t8v[k] = sv; t8i[k] = bi;
                    g_aidx[bt * TOPKK + k] = bi;
                    g_aval[bt * TOPKK + k] = sv;
                }
                if (i0 == bi) v0 = -1.f;
                if (i1 == bi) v1 = -1.f;
            }
        }
        __syncthreads();
        // ---- c update ----
        float ac = 0.f;
        #pragma unroll
        for (int j = 0; j < TOPKK; j++)
            if (t8i[j] == c) ac = t8v[j];
        float vv = valid[bt];
        float cn = RHOf * cp + (1.f - RHOf) * ac;
        cp = vv * cn + (1.f - vv) * cp;
        g_ct[bt * Cdim + c] = cp;
        g_A[(size_t)bt * AP + Mdim + c] = cp;
    }
    asm volatile("cp.async.wait_group 0;" ::: "memory");
    __syncthreads();
}

// ---------------- K3b: pre-split A rows into bf16 hi/lo --------------------
__global__ void k_acvt() {
    int r = blockIdx.x, tid = threadIdx.x;
    __nv_bfloat16* ph = (__nv_bfloat16*)g_Abf_hi4;
    __nv_bfloat16* pl = (__nv_bfloat16*)g_Abf_lo4;
    for (int j = tid; j < 768; j += 256) {
        float v = g_A[(size_t)r * AP + j];
        __nv_bfloat16 h = __float2bfloat16_rn(v);
        ph[r * 768 + j] = h;
        pl[r * 768 + j] = __float2bfloat16_rn(v - __bfloat162float(h));
    }
}

// ---------------- K4: pipelined cand GEMM (mma.sync bf16x3) ----------------
#define SOFF_A 0            // 4 x 20480: hi0, lo0, hi1, lo1
#define SOFF_W_HI 81920
#define SOFF_W_LO 87040
#define SOFF_BIAS 92160
#define K4_SMEM   92416
#define APITCH 80   // bytes per smem A/W row (32 bf16 + 8 pad)

__device__ __forceinline__ void stage_A(uint32_t sb, int buf, int k0, int tid) {
    uint32_t hbase = sb + SOFF_A + buf * 40960;
    uint32_t lbase = hbase + 20480;
    #pragma unroll
    for (int i = 0; i < 4; i++) {
        int s = tid + i * 256;
        int row = s >> 2, qq = s & 3;
        size_t soff = ((size_t)row * 768 + k0) * 2 + qq * 16;
        cpasync16(hbase + row * APITCH + qq * 16, (const char*)g_Abf_hi4 + soff);
        cpasync16(lbase + row * APITCH + qq * 16, (const char*)g_Abf_lo4 + soff);
    }
}
__device__ __forceinline__ void ldW(const float* __restrict__ Wu, const float* __restrict__ Wc,
                                    int n0, int q, int tid, float4* w) {
    int k0 = q * 32; const float* Wp; int sw;
    if (k0 < 512) { Wp = Wu + k0; sw = 512; } else { Wp = Wc + (k0 - 512); sw = 256; }
    #pragma unroll
    for (int i = 0; i < 2; i++) {
        int s = tid + i * 256;
        int row = s >> 3, c4 = (s & 7) * 4;
        w[i] = *(const float4*)(Wp + (size_t)(n0 + row) * sw + c4);
    }
}

__global__ void __launch_bounds__(256, 2)
k4_mma(const float* __restrict__ Wu, const float* __restrict__ Wc,
       const float* __restrict__ bu, const float* __restrict__ bc) {
    extern __shared__ char sm[];
    uint32_t sb = smem_u32(sm);
    int tid = threadIdx.x, wid = tid >> 5, lane = tid & 31;
    int wm = wid & 3, wn = wid >> 2;
    int n0 = blockIdx.x * 64;

    if (tid < 64) ((float*)(sm + SOFF_BIAS))[tid] = bu[n0 + tid] + bc[n0 + tid];

    float acc[4][4][4];
    #pragma unroll
    for (int i = 0; i < 4; i++)
        #pragma unroll
        for (int j = 0; j < 4; j++)
            #pragma unroll
            for (int k = 0; k < 4; k++) acc[i][j][k] = 0.f;

    uint32_t aoff[4], boff[2];
    #pragma unroll
    for (int mt = 0; mt < 4; mt++)
        aoff[mt] = (uint32_t)((wm * 64 + mt * 16 + (lane & 15)) * APITCH + (lane >> 4) * 16);
    #pragma unroll
    for (int np = 0; np < 2; np++)
        boff[np] = (uint32_t)((wn * 32 + np * 16 + (lane & 7) + ((lane >> 4) << 3)) * APITCH
                              + ((lane >> 3) & 1) * 16);

    stage_A(sb, 0, 0, tid);
    asm volatile("cp.async.commit_group;" ::: "memory");
    float4 wreg[2];
    ldW(Wu, Wc, n0, 0, tid, wreg);

    for (int q = 0; q < 24; q++) {
        int buf = q & 1;
        __syncthreads();
        #pragma unroll
        for (int i = 0; i < 2; i++) {
            int s = tid + i * 256;
            int row = s >> 3, c4 = (s & 7) * 4;
            float4 v = wreg[i];
            __nv_bfloat16 h0 = __float2bfloat16_rn(v.x), h1 = __float2bfloat16_rn(v.y);
            __nv_bfloat16 h2 = __float2bfloat16_rn(v.z), h3 = __float2bfloat16_rn(v.w);
            uint2 hi, lo;
            hi.x = (uint32_t)__bfloat16_as_ushort(h0) | ((uint32_t)__bfloat16_as_ushort(h1) << 16);
            hi.y = (uint32_t)__bfloat16_as_ushort(h2) | ((uint32_t)__bfloat16_as_ushort(h3) << 16);
            __nv_bfloat16 l0 = __float2bfloat16_rn(v.x - __bfloat162float(h0));
            __nv_bfloat16 l1 = __float2bfloat16_rn(v.y - __bfloat162float(h1));
            __nv_bfloat16 l2 = __float2bfloat16_rn(v.z - __bfloat162float(h2));
            __nv_bfloat16 l3 = __float2bfloat16_rn(v.w - __bfloat162float(h3));
            lo.x = (uint32_t)__bfloat16_as_ushort(l0) | ((uint32_t)__bfloat16_as_ushort(l1) << 16);
            lo.y = (uint32_t)__bfloat16_as_ushort(l2) | ((uint32_t)__bfloat16_as_ushort(l3) << 16);
            *(uint2*)(sm + SOFF_W_HI + row * APITCH + c4 * 2) = hi;
            *(uint2*)(sm + SOFF_W_LO + row * APITCH + c4 * 2) = lo;
        }
        if (q + 1 < 24) {
            stage_A(sb, buf ^ 1, (q + 1) * 32, tid);
            asm volatile("cp.async.commit_group;" ::: "memory");
            ldW(Wu, Wc, n0, q + 1, tid, wreg);
            asm volatile("cp.async.wait_group 1;" ::: "memory");
        } else {
            asm volatile("cp.async.wait_group 0;" ::: "memory");
        }
        __syncthreads();
        uint32_t abh = sb + SOFF_A + buf * 40960;
        uint32_t abl = abh + 20480;
        #pragma unroll
        for (int kh = 0; kh < 2; kh++) {
            uint32_t ah[4][4], al[4][4];
            #pragma unroll
            for (int mt = 0; mt < 4; mt++) {
                ldsm_x4(ah[mt], abh + aoff[mt] + kh * 32);
                ldsm_x4(al[mt], abl + aoff[mt] + kh * 32);
            }
            #pragma unroll
            for (int np = 0; np < 2; np++) {
                uint32_t bh[4], bl[4];
                ldsm_x4(bh, sb + SOFF_W_HI + boff[np] + kh * 32);
                ldsm_x4(bl, sb + SOFF_W_LO + boff[np] + kh * 32);
                #pragma unroll
                for (int h = 0; h < 2; h++) {
                    #pragma unroll
                    for (int mt = 0; mt < 4; mt++)
                        mma_bf16(acc[mt][np * 2 + h], ah[mt], bh[h * 2], bh[h * 2 + 1]);
                    #pragma unroll
                    for (int mt = 0; mt < 4; mt++)
                        mma_bf16(acc[mt][np * 2 + h], ah[mt], bl[h * 2], bl[h * 2 + 1]);
                    #pragma unroll
                    for (int mt = 0; mt < 4; mt++)
                        mma_bf16(acc[mt][np * 2 + h], al[mt], bh[h * 2], bh[h * 2 + 1]);
                }
            }
        }
    }
    const float* bias = (const float*)(sm + SOFF_BIAS);
    #pragma unroll
    for (int mt = 0; mt < 4; mt++) {
        int row = wm * 64 + mt * 16 + (lane >> 2);
        #pragma unroll
        for (int nf = 0; nf < 4; nf++) {
            int cl = wn * 32 + nf * 8 + (lane & 3) * 2;
            float b0 = bias[cl], b1 = bias[cl + 1];
            float2 v0 = make_float2(acc[mt][nf][0] + b0, acc[mt][nf][1] + b1);
            float2 v1 = make_float2(acc[mt][nf][2] + b0, acc[mt][nf][3] + b1);
            *(float2*)(g_cand + (size_t)row * MC + n0 + cl)       = v0;
            *(float2*)(g_cand + (size_t)(row + 8) * MC + n0 + cl) = v1;
        }
    }
}

// ---------------- K5: D0 init + barrier reset ------------------------------
__global__ void k5_dinit(const float* __restrict__ base) {
    __shared__ float sh[8];
    int c = blockIdx.x, tid = threadIdx.x;  // 128 threads
    if (c < Bdim && tid == 0) g_bar[c] = 0;
    float s = 0.f;
    for (int m = tid; m < Mdim; m += 128) {
        float v = base[(size_t)m * Cdim + c];
        s += v * v;
    }
    float stot = blockReduceSum(s, sh);
    float inv = 1.f / fmaxf(sqrtf(stot), EPSF);
    for (int b = 0; b < Bdim; b++)
        for (int m = tid; m < Mdim; m += 128)
            g_D[0][((size_t)b * Cdim + c) * Mdim + m] = base[(size_t)m * Cdim + c] * inv;
}

// ---------------- K6: persistent dictionary-update steps + fused output ----
__global__ void __launch_bounds__(256, 2)
k_steps(const float* __restrict__ u, const float* __restrict__ valid,
        const float* __restrict__ Wg, const float* __restrict__ bg,
        float* __restrict__ out) {
    __shared__ float sh[8];
    __shared__ float rsh[Mdim];
    __shared__ float ctsh[Cdim];
    __shared__ float cnd[CPT][CPITCH];
    __shared__ int   aidx[TOPKK];
    __shared__ float aval[TOPKK];
    __shared__ float gsh;
    int tile = blockIdx.x, b = blockIdx.y, tid = threadIdx.x;
    int c0 = tile * CPT;
    int w = tid >> 5, lane = tid & 31;
    int cc = c0 + w;

    for (int t = 0; t < Tdim; t++) {
        int sbuf = t & 1;
        const float* Dsrc = g_D[sbuf];
        float*       Ddst = g_D[sbuf ^ 1];
        int bt = b * Tdim + t;
        const float* ur = u + (size_t)bt * Mdim;
        float vv = valid[bt];
        ctsh[tid] = g_ct[bt * Cdim + tid];
        if (tid < TOPKK) { aidx[tid] = g_aidx[bt * TOPKK + tid]; aval[tid] = g_aval[bt * TOPKK + tid]; }
        __syncthreads();
        float perr = 0.f, pg = 0.f;
        #pragma unroll
        for (int h = 0; h < 2; h++) {
            int m = tid + h * 256;
            float acc = ur[m];
            #pragma unroll
            for (int j = 0; j < TOPKK; j++)
                acc -= Dsrc[((size_t)b * Cdim + aidx[j]) * Mdim + m] * aval[j];
            rsh[m] = acc;
            perr += acc * acc;
            pg   += Wg[m] * ur[m];
        }
        pg += Wg[Mdim + tid] * ctsh[tid];
        const float* cb = g_cand + (size_t)bt * MC + c0;
        for (int i = tid; i < Mdim * CPT; i += 256) {
            int mm = i >> 3, j = i & 7;
            cnd[j][mm] = cb[(size_t)mm * Cdim + j];
        }
        float errsum = blockReduceSum(perr, sh);
        float gsum   = blockReduceSum(pg, sh);
        if (tid == 0) {
            float err = sqrtf(errsum);
            float gp  = gsum + Wg[Mdim + Cdim] * err + bg[0];
            gsh = 1.f / (1.f + expf(-gp));
        }
        __syncthreads();
        float g = gsh;
        float av = 0.f;
        #pragma unroll
        for (int j = 0; j < TOPKK; j++)
            if (aidx[j] == cc) av = aval[j];
        const float* Dc = Dsrc + ((size_t)b * Cdim + cc) * Mdim;
        float*       Do = Ddst + ((size_t)b * Cdim + cc) * Mdim;
        float Dreg[16];
        float sl = 0.f, sc2 = 0.f, sx = 0.f;
        float dla = DLRf * av;
        #pragma unroll
        for (int k = 0; k < 16; k++) {
            int m = lane + 32 * k;
            float dd = Dc[m]; Dreg[k] = dd;
            float dl = fmaf(dla, rsh[m], dd);
            float cn = cnd[w][m];
            sl  = fmaf(dl, dl, sl);
            sc2 = fmaf(cn, cn, sc2);
            sx  = fmaf(dl, cn, sx);
        }
        #pragma unroll
        for (int o = 16; o; o >>= 1) {
            sl  += __shfl_xor_sync(0xffffffffu, sl,  o);
            sc2 += __shfl_xor_sync(0xffffffffu, sc2, o);
            sx  += __shfl_xor_sync(0xffffffffu, sx,  o);
        }
        float il  = 1.f / fmaxf(sqrtf(sl),  EPSF);
        float icn = 1.f / fmaxf(sqrtf(sc2), EPSF);
        float w1 = (1.f - g) * il, w2 = g * icn;
        float smix = w1 * w1 * sl + 2.f * w1 * w2 * sx + w2 * w2 * sc2;
        float imix = 1.f / fmaxf(sqrtf(smix), EPSF);
        float ctc = ctsh[cc];
        #pragma unroll
        for (int k = 0; k < 16; k++) {
            int m = lane + 32 * k;
            float dl  = fmaf(dla, rsh[m], Dreg[k]);
            float cn  = cnd[w][m];
            float mix = w1 * dl + w2 * cn;
            float dn  = vv * (mix * imix) + (1.f - vv) * Dreg[k];
            Do[m] = dn;
            cnd[w][m] = dn * ctc;
        }
        __syncthreads();
        float* zp = g_zpart + ((size_t)bt * NTILE + tile) * Mdim;
        for (int m = tid; m < Mdim; m += 256) {
            float z = 0.f;
            #pragma unroll
            for (int j = 0; j < CPT; j++) z += cnd[j][m];
            zp[m] = z;
        }
        __threadfence();
        __syncthreads();
        if (tid == 0) atomicAdd(&g_bar[b], 1u);
        if (t + 1 < Tdim) {
            if (tid == 0) {
                unsigned tgt = (unsigned)((t + 1) * NTILE);
                while (atomicAdd(&g_bar[b], 0u) < tgt) __nanosleep(32);
            }
            __syncthreads();
            __threadfence();
        }
    }
    // ---- fused output: wait for all tiles of batch b, reduce z for one bt --
    if (tid == 0) {
        while (atomicAdd(&g_bar[b], 0u) < (unsigned)(Tdim * NTILE)) __nanosleep(32);
    }
    __syncthreads();
    __threadfence();
    int obt = b * Tdim + tile;       // NTILE == Tdim == 32
    const float* zp = g_zpart + (size_t)obt * NTILE * Mdim;
    for (int m = tid; m < Mdim; m += 256) {
        float s = 0.f;
        #pragma unroll
        for (int j = 0; j < NTILE; j++) s += zp[(size_t)j * Mdim + m];
        out[obt * Mdim + m] = s;
    }
}

// ---------------- launch ---------------------------------------------------
extern "C" void kernel_launch(void* const* d_in, const int* in_sizes, int n_in,
                              void* d_out, int out_size) {
    const float* u       = (const float*)d_in[0];
    const float* valid   = (const float*)d_in[1];
    const float* base    = (const float*)d_in[2];
    const float* Wcu     = (const float*)d_in[3];
    const float* Wcc     = (const float*)d_in[4];
    const float* Wcand_u = (const float*)d_in[5];
    const float* bcand_u = (const float*)d_in[6];
    const float* Wcand_c = (const float*)d_in[7];
    const float* bcand_c = (const float*)d_in[8];
    const float* Wg      = (const float*)d_in[9];
    const float* bg      = (const float*)d_in[10];
    const float* lnug    = (const float*)d_in[11];
    const float* lnub    = (const float*)d_in[12];
    const float* lncg    = (const float*)d_in[13];
    const float* lncb    = (const float*)d_in[14];
    float* out = (float*)d_out;

    cudaFuncSetAttribute(k4_mma, cudaFuncAttributeMaxDynamicSharedMemorySize, K4_SMEM);
    cudaFuncSetAttribute(k3_rec, cudaFuncAttributeMaxDynamicSharedMemorySize, K3_SMEM);

    k5_dinit<<<Cdim, 128>>>(base);
    k1_lnu<<<BT, 256>>>(u, lnug, lnub);
    k2_lu <<<BT, 256>>>(Wcu);
    k3_rec<<<Bdim, 256, K3_SMEM>>>(Wcc, valid, lncg, lncb);
    k_acvt<<<BT, 256>>>();
    k4_mma<<<MC / 64, 256, K4_SMEM>>>(Wcand_u, Wcand_c, bcand_u, bcand_c);
    k_steps<<<dim3(NTILE, Bdim), 256>>>(u, valid, Wg, bg, out);
}

// round 8
// speedup vs baseline: 2.0560x; 1.0785x over previous
#include <cuda_runtime.h>
#include <cuda_bf16.h>
#include <cstdint>

#define Mdim 512
#define Cdim 256
#define Bdim 8
#define Tdim 32
#define BT 256            // B*T
#define MC 131072         // M*C
#define TOPKK 8
#define LAMf 0.05f
#define RHOf 0.9f
#define DLRf 0.03f
#define EPSF 1e-12f
#define LN_EPSF 1e-5f
#define AP 776            // padded A row pitch (floats)
#define NTILE 32          // C / 8 column tiles
#define CPT 8             // columns per tile
#define CPITCH 520        // smem cand pitch

// ---------------- scratch (device globals; no allocation allowed) ----------
__device__ float g_LNu[BT * Mdim];
__device__ float g_A[BT * AP];                     // [u(512) | c_t(256)] rows
__device__ float g_Lu[BT * Cdim];
__device__ float g_ct[BT * Cdim];
__device__ int   g_aidx[BT * TOPKK];
__device__ float g_aval[BT * TOPKK];
__device__ float g_cand[(size_t)BT * MC];          // 128 MiB cand scratch
__device__ float g_D[2][Bdim * Cdim * Mdim];       // ping-pong dictionary [b][c][m]
__device__ float g_zpart[(size_t)BT * NTILE * Mdim];
__device__ unsigned g_bar[Bdim];                   // per-batch step barriers
__device__ uint4 g_Abf_hi4[BT * 768 * 2 / 16];     // A hi bf16 (16B-aligned)
__device__ uint4 g_Abf_lo4[BT * 768 * 2 / 16];     // A lo bf16

// ---------------- helpers --------------------------------------------------
__device__ __forceinline__ uint32_t smem_u32(const void* p) {
    uint32_t a;
    asm("{ .reg .u64 t; cvta.to.shared.u64 t, %1; cvt.u32.u64 %0, t; }" : "=r"(a) : "l"(p));
    return a;
}
__device__ __forceinline__ void ldsm_x4(uint32_t* r, uint32_t addr) {
    asm volatile("ldmatrix.sync.aligned.m8n8.x4.shared.b16 {%0,%1,%2,%3}, [%4];"
        : "=r"(r[0]), "=r"(r[1]), "=r"(r[2]), "=r"(r[3]) : "r"(addr));
}
__device__ __forceinline__ void mma_bf16(float* c, const uint32_t* a, uint32_t b0, uint32_t b1) {
    asm volatile("mma.sync.aligned.m16n8k16.row.col.f32.bf16.bf16.f32 "
        "{%0,%1,%2,%3}, {%4,%5,%6,%7}, {%8,%9}, {%0,%1,%2,%3};"
        : "+f"(c[0]), "+f"(c[1]), "+f"(c[2]), "+f"(c[3])
        : "r"(a[0]), "r"(a[1]), "r"(a[2]), "r"(a[3]), "r"(b0), "r"(b1));
}
__device__ __forceinline__ void cpasync16(uint32_t dst, const void* src) {
    asm volatile("cp.async.cg.shared.global [%0], [%1], 16;" :: "r"(dst), "l"(src));
}
__device__ __forceinline__ float blockReduceSum(float v, float* sh) {
    __syncthreads();
    #pragma unroll
    for (int o = 16; o; o >>= 1) v += __shfl_xor_sync(0xffffffffu, v, o);
    int w = threadIdx.x >> 5, l = threadIdx.x & 31;
    if (l == 0) sh[w] = v;
    __syncthreads();
    if (w == 0) {
        float x = (l < (int)(blockDim.x >> 5)) ? sh[l] : 0.f;
        #pragma unroll
        for (int o = 4; o; o >>= 1) x += __shfl_xor_sync(0xffffffffu, x, o);
        if (l == 0) sh[0] = x;
    }
    __syncthreads();
    return sh[0];
}

// ---------------- K1: LN(u), fill A u-part ---------------------------------
__global__ void k1_lnu(const float* __restrict__ u,
                       const float* __restrict__ g, const float* __restrict__ bb) {
    __shared__ float sh[8];
    int r = blockIdx.x, tid = threadIdx.x;
    const float* ur = u + (size_t)r * Mdim;
    float x0 = ur[tid], x1 = ur[tid + 256];
    float s = blockReduceSum(x0 + x1, sh);
    float mu = s * (1.f / Mdim);
    float d0 = x0 - mu, d1 = x1 - mu;
    float var = blockReduceSum(d0 * d0 + d1 * d1, sh) * (1.f / Mdim);
    float inv = rsqrtf(var + LN_EPSF);
    g_LNu[(size_t)r * Mdim + tid]       = d0 * inv * g[tid] + bb[tid];
    g_LNu[(size_t)r * Mdim + tid + 256] = d1 * inv * g[tid + 256] + bb[tid + 256];
    g_A[(size_t)r * AP + tid]       = x0;
    g_A[(size_t)r * AP + tid + 256] = x1;
}

// ---------------- K2: Lu = LN(u) @ W_cu^T ---------------------------------
__global__ void k2_lu(const float* __restrict__ Wcu) {
    __shared__ float ln[Mdim];
    int r = blockIdx.x, c = threadIdx.x;
    ln[c]       = g_LNu[(size_t)r * Mdim + c];
    ln[c + 256] = g_LNu[(size_t)r * Mdim + c + 256];
    __syncthreads();
    const float4* wr = (const float4*)(Wcu + (size_t)c * Mdim);
    float a0 = 0.f, a1 = 0.f, a2 = 0.f, a3 = 0.f;
    #pragma unroll 4
    for (int i = 0; i < 128; i += 4) {
        float4 w0 = wr[i],   w1 = wr[i+1], w2 = wr[i+2], w3 = wr[i+3];
        a0 = fmaf(w0.x, ln[4*i+0], fmaf(w0.y, ln[4*i+1], fmaf(w0.z, ln[4*i+2], fmaf(w0.w, ln[4*i+3], a0))));
        a1 = fmaf(w1.x, ln[4*i+4], fmaf(w1.y, ln[4*i+5], fmaf(w1.z, ln[4*i+6], fmaf(w1.w, ln[4*i+7], a1))));
        a2 = fmaf(w2.x, ln[4*i+8], fmaf(w2.y, ln[4*i+9], fmaf(w2.z, ln[4*i+10], fmaf(w2.w, ln[4*i+11], a2))));
        a3 = fmaf(w3.x, ln[4*i+12], fmaf(w3.y, ln[4*i+13], fmaf(w3.z, ln[4*i+14], fmaf(w3.w, ln[4*i+15], a3))));
    }
    g_Lu[r * Cdim + c] = (a0 + a1) + (a2 + a3);
}

// ---------------- K3: sparse-code recurrence, smem-tiled GEMV --------------
// Wcc streamed through 2 x 64KB smem buffers via 16B cp.async.
// float4-granular XOR swizzle: row r, float4 group p stored at p^(r&15).
#define K3_TILE 65536
#define K3_SMEM (2 * K3_TILE)

__device__ __forceinline__ void k3_load_tile(uint32_t base, const float* __restrict__ Wcc,
                                             int kt, int tid) {
    int rg = tid >> 4;        // 0..15
    int j4 = tid & 15;        // float4 col within 64-col tile
    #pragma unroll
    for (int i = 0; i < 16; i++) {
        int row = rg + 16 * i;
        int p = j4 ^ (row & 15);
        cpasync16(base + (uint32_t)(row * 256 + p * 16),
                  Wcc + (size_t)row * Cdim + kt + j4 * 4);
    }
    asm volatile("cp.async.commit_group;" ::: "memory");
}

__global__ void __launch_bounds__(256, 1)
k3_rec(const float* __restrict__ Wcc, const float* __restrict__ valid,
       const float* __restrict__ lncg, const float* __restrict__ lncb) {
    extern __shared__ char k3sm[];
    uint32_t wsb = smem_u32(k3sm);
    __shared__ float sh[16];
    __shared__ float lnc[Cdim];
    __shared__ float shr_sm[Cdim];
    __shared__ float cwv[64];
    __shared__ int   cwi[64];
    __shared__ float t8v[TOPKK];
    __shared__ int   t8i[TOPKK];
    int b = blockIdx.x, c = threadIdx.x;
    int w = c >> 5, lane = c & 31;
    float cp = 0.f;
    float gC = lncg[c], bC = lncb[c];

    // prologue: tiles 0 (buf0) and 1 (buf1) in flight
    k3_load_tile(wsb, Wcc, 0, c);
    k3_load_tile(wsb + K3_TILE, Wcc, 64, c);

    for (int t = 0; t < Tdim; t++) {
        int bt = b * Tdim + t;
        // ---- fused LN reduction ----
        float s1 = cp, s2 = cp * cp;
        #pragma unroll
        for (int o = 16; o; o >>= 1) {
            s1 += __shfl_xor_sync(0xffffffffu, s1, o);
            s2 += __shfl_xor_sync(0xffffffffu, s2, o);
        }
        if (lane == 0) { sh[w] = s1; sh[8 + w] = s2; }
        __syncthreads();
        float t1 = 0.f, t2 = 0.f;
        #pragma unroll
        for (int j = 0; j < 8; j++) { t1 += sh[j]; t2 += sh[8 + j]; }
        float mu  = t1 * (1.f / Cdim);
        float var = t2 * (1.f / Cdim) - mu * mu;
        float inv = rsqrtf(var + LN_EPSF);
        lnc[c] = (cp - mu) * inv * gC + bC;
        // ---- GEMV over 4 streamed tiles ----
        float acc = g_Lu[bt * Cdim + c];
        const char* rowbase0 = k3sm + c * 256;
        int cm = c & 15;
        #pragma unroll
        for (int tile = 0; tile < 4; tile++) {
            int buf = tile & 1;
            asm volatile("cp.async.wait_group 1;" ::: "memory");
            __syncthreads();           // tile data + lnc visible to all
            const char* wb = rowbase0 + buf * K3_TILE;
            const float2* lv = (const float2*)(lnc + tile * 64);
            float a0 = 0.f, a1 = 0.f, a2 = 0.f, a3 = 0.f;
            #pragma unroll
            for (int j = 0; j < 32; j += 4) {
                float2 w0 = *(const float2*)(wb + (((j    >> 1) ^ cm) * 16 + ((j    ) & 1) * 8));
                float2 w1 = *(const float2*)(wb + ((((j+1) >> 1) ^ cm) * 16 + ((j+1) & 1) * 8));
                float2 w2 = *(const float2*)(wb + ((((j+2) >> 1) ^ cm) * 16 + ((j+2) & 1) * 8));
                float2 w3 = *(const float2*)(wb + ((((j+3) >> 1) ^ cm) * 16 + ((j+3) & 1) * 8));
                float2 l0 = lv[j], l1 = lv[j+1], l2 = lv[j+2], l3 = lv[j+3];
                a0 = fmaf(w0.x, l0.x, fmaf(w0.y, l0.y, a0));
                a1 = fmaf(w1.x, l1.x, fmaf(w1.y, l1.y, a1));
                a2 = fmaf(w2.x, l2.x, fmaf(w2.y, l2.y, a2));
                a3 = fmaf(w3.x, l3.x, fmaf(w3.y, l3.y, a3));
            }
            acc += (a0 + a1) + (a2 + a3);
            __syncthreads();           // everyone done reading buf before refill
            int nk = ((tile + 2) & 3) * 64;
            k3_load_tile(wsb + buf * K3_TILE, Wcc, nk, c);
        }
        // ---- shrink ----
        float aa  = fabsf(acc) - LAMf;
        float shr = aa > 0.f ? copysignf(aa, acc) : 0.f;
        shr_sm[c] = shr;
        // ---- warp-local top-8 ----
        float myv = fabsf(shr); int myi = c;
        #pragma unroll
        for (int k = 0; k < TOPKK; k++) {
            float mv = myv; int mi = myi;
            #pragma unroll
            for (int o = 16; o; o >>= 1) {
                float ov = __shfl_xor_sync(0xffffffffu, mv, o);
                int   oi = __shfl_xor_sync(0xffffffffu, mi, o);
                if (ov > mv || (ov == mv && oi < mi)) { mv = ov; mi = oi; }
            }
            if (lane == 0) { cwv[w * 8 + k] = mv; cwi[w * 8 + k] = mi; }
            if (myi == mi) myv = -1.f;
        }
        __syncthreads();
        // ---- warp-0 merge -> global top-8 ----
        if (w == 0) {
            float v0 = cwv[lane], v1 = cwv[32 + lane];
            int   i0 = cwi[lane], i1 = cwi[32 + lane];
            #pragma unroll
            for (int k = 0; k < TOPKK; k++) {
                float bv; int bi;
                if (v0 > v1 || (v0 == v1 && i0 < i1)) { bv = v0; bi = i0; }
                else                                   { bv = v1; bi = i1; }
                #pragma unroll
                for (int o = 16; o; o >>= 1) {
                    float ov = __shfl_xor_sync(0xffffffffu, bv, o);
                    int   oi = __shfl_xor_sync(0xffffffffu, bi, o);
                    if (ov > bv || (ov == bv && oi < bi)) { bv = ov; bi = oi; }
                }
                if (lane == 0) {
                    float sv = shr_sm[bi];
                    t8v[k] = sv; t8i[k] = bi;
                    g_aidx[bt * TOPKK + k] = bi;
                    g_aval[bt * TOPKK + k] = sv;
                }
                if (i0 == bi) v0 = -1.f;
                if (i1 == bi) v1 = -1.f;
            }
        }
        __syncthreads();
        // ---- c update ----
        float ac = 0.f;
        #pragma unroll
        for (int j = 0; j < TOPKK; j++)
            if (t8i[j] == c) ac = t8v[j];
        float vv = valid[bt];
        float cn = RHOf * cp + (1.f - RHOf) * ac;
        cp = vv * cn + (1.f - vv) * cp;
        g_ct[bt * Cdim + c] = cp;
        g_A[(size_t)bt * AP + Mdim + c] = cp;
    }
    asm volatile("cp.async.wait_group 0;" ::: "memory");
    __syncthreads();
}

// ---------------- K3b: pre-split A rows into bf16 hi/lo --------------------
__global__ void k_acvt() {
    int r = blockIdx.x, tid = threadIdx.x;
    __nv_bfloat16* ph = (__nv_bfloat16*)g_Abf_hi4;
    __nv_bfloat16* pl = (__nv_bfloat16*)g_Abf_lo4;
    for (int j = tid; j < 768; j += 256) {
        float v = g_A[(size_t)r * AP + j];
        __nv_bfloat16 h = __float2bfloat16_rn(v);
        ph[r * 768 + j] = h;
        pl[r * 768 + j] = __float2bfloat16_rn(v - __bfloat162float(h));
    }
}

// ---------------- K4: pipelined cand GEMM (mma.sync bf16x3) ----------------
#define SOFF_A 0            // 4 x 20480: hi0, lo0, hi1, lo1
#define SOFF_W_HI 81920
#define SOFF_W_LO 87040
#define SOFF_BIAS 92160
#define K4_SMEM   92416
#define APITCH 80   // bytes per smem A/W row (32 bf16 + 8 pad)

__device__ __forceinline__ void stage_A(uint32_t sb, int buf, int k0, int tid) {
    uint32_t hbase = sb + SOFF_A + buf * 40960;
    uint32_t lbase = hbase + 20480;
    #pragma unroll
    for (int i = 0; i < 4; i++) {
        int s = tid + i * 256;
        int row = s >> 2, qq = s & 3;
        size_t soff = ((size_t)row * 768 + k0) * 2 + qq * 16;
        cpasync16(hbase + row * APITCH + qq * 16, (const char*)g_Abf_hi4 + soff);
        cpasync16(lbase + row * APITCH + qq * 16, (const char*)g_Abf_lo4 + soff);
    }
}
__device__ __forceinline__ void ldW(const float* __restrict__ Wu, const float* __restrict__ Wc,
                                    int n0, int q, int tid, float4* w) {
    int k0 = q * 32; const float* Wp; int sw;
    if (k0 < 512) { Wp = Wu + k0; sw = 512; } else { Wp = Wc + (k0 - 512); sw = 256; }
    #pragma unroll
    for (int i = 0; i < 2; i++) {
        int s = tid + i * 256;
        int row = s >> 3, c4 = (s & 7) * 4;
        w[i] = *(const float4*)(Wp + (size_t)(n0 + row) * sw + c4);
    }
}

__global__ void __launch_bounds__(256, 2)
k4_mma(const float* __restrict__ Wu, const float* __restrict__ Wc,
       const float* __restrict__ bu, const float* __restrict__ bc) {
    extern __shared__ char sm[];
    uint32_t sb = smem_u32(sm);
    int tid = threadIdx.x, wid = tid >> 5, lane = tid & 31;
    int wm = wid & 3, wn = wid >> 2;
    int n0 = blockIdx.x * 64;

    if (tid < 64) ((float*)(sm + SOFF_BIAS))[tid] = bu[n0 + tid] + bc[n0 + tid];

    float acc[4][4][4];
    #pragma unroll
    for (int i = 0; i < 4; i++)
        #pragma unroll
        for (int j = 0; j < 4; j++)
            #pragma unroll
            for (int k = 0; k < 4; k++) acc[i][j][k] = 0.f;

    uint32_t aoff[4], boff[2];
    #pragma unroll
    for (int mt = 0; mt < 4; mt++)
        aoff[mt] = (uint32_t)((wm * 64 + mt * 16 + (lane & 15)) * APITCH + (lane >> 4) * 16);
    #pragma unroll
    for (int np = 0; np < 2; np++)
        boff[np] = (uint32_t)((wn * 32 + np * 16 + (lane & 7) + ((lane >> 4) << 3)) * APITCH
                              + ((lane >> 3) & 1) * 16);

    stage_A(sb, 0, 0, tid);
    asm volatile("cp.async.commit_group;" ::: "memory");
    float4 wreg[2];
    ldW(Wu, Wc, n0, 0, tid, wreg);

    for (int q = 0; q < 24; q++) {
        int buf = q & 1;
        __syncthreads();
        #pragma unroll
        for (int i = 0; i < 2; i++) {
            int s = tid + i * 256;
            int row = s >> 3, c4 = (s & 7) * 4;
            float4 v = wreg[i];
            __nv_bfloat16 h0 = __float2bfloat16_rn(v.x), h1 = __float2bfloat16_rn(v.y);
            __nv_bfloat16 h2 = __float2bfloat16_rn(v.z), h3 = __float2bfloat16_rn(v.w);
            uint2 hi, lo;
            hi.x = (uint32_t)__bfloat16_as_ushort(h0) | ((uint32_t)__bfloat16_as_ushort(h1) << 16);
            hi.y = (uint32_t)__bfloat16_as_ushort(h2) | ((uint32_t)__bfloat16_as_ushort(h3) << 16);
            __nv_bfloat16 l0 = __float2bfloat16_rn(v.x - __bfloat162float(h0));
            __nv_bfloat16 l1 = __float2bfloat16_rn(v.y - __bfloat162float(h1));
            __nv_bfloat16 l2 = __float2bfloat16_rn(v.z - __bfloat162float(h2));
            __nv_bfloat16 l3 = __float2bfloat16_rn(v.w - __bfloat162float(h3));
            lo.x = (uint32_t)__bfloat16_as_ushort(l0) | ((uint32_t)__bfloat16_as_ushort(l1) << 16);
            lo.y = (uint32_t)__bfloat16_as_ushort(l2) | ((uint32_t)__bfloat16_as_ushort(l3) << 16);
            *(uint2*)(sm + SOFF_W_HI + row * APITCH + c4 * 2) = hi;
            *(uint2*)(sm + SOFF_W_LO + row * APITCH + c4 * 2) = lo;
        }
        if (q + 1 < 24) {
            stage_A(sb, buf ^ 1, (q + 1) * 32, tid);
            asm volatile("cp.async.commit_group;" ::: "memory");
            ldW(Wu, Wc, n0, q + 1, tid, wreg);
            asm volatile("cp.async.wait_group 1;" ::: "memory");
        } else {
            asm volatile("cp.async.wait_group 0;" ::: "memory");
        }
        __syncthreads();
        uint32_t abh = sb + SOFF_A + buf * 40960;
        uint32_t abl = abh + 20480;
        #pragma unroll
        for (int kh = 0; kh < 2; kh++) {
            uint32_t ah[4][4], al[4][4];
            #pragma unroll
            for (int mt = 0; mt < 4; mt++) {
                ldsm_x4(ah[mt], abh + aoff[mt] + kh * 32);
                ldsm_x4(al[mt], abl + aoff[mt] + kh * 32);
            }
            #pragma unroll
            for (int np = 0; np < 2; np++) {
                uint32_t bh[4], bl[4];
                ldsm_x4(bh, sb + SOFF_W_HI + boff[np] + kh * 32);
                ldsm_x4(bl, sb + SOFF_W_LO + boff[np] + kh * 32);
                #pragma unroll
                for (int h = 0; h < 2; h++) {
                    #pragma unroll
                    for (int mt = 0; mt < 4; mt++)
                        mma_bf16(acc[mt][np * 2 + h], ah[mt], bh[h * 2], bh[h * 2 + 1]);
                    #pragma unroll
                    for (int mt = 0; mt < 4; mt++)
                        mma_bf16(acc[mt][np * 2 + h], ah[mt], bl[h * 2], bl[h * 2 + 1]);
                    #pragma unroll
                    for (int mt = 0; mt < 4; mt++)
                        mma_bf16(acc[mt][np * 2 + h], al[mt], bh[h * 2], bh[h * 2 + 1]);
                }
            }
        }
    }
    const float* bias = (const float*)(sm + SOFF_BIAS);
    #pragma unroll
    for (int mt = 0; mt < 4; mt++) {
        int row = wm * 64 + mt * 16 + (lane >> 2);
        #pragma unroll
        for (int nf = 0; nf < 4; nf++) {
            int cl = wn * 32 + nf * 8 + (lane & 3) * 2;
            float b0 = bias[cl], b1 = bias[cl + 1];
            float2 v0 = make_float2(acc[mt][nf][0] + b0, acc[mt][nf][1] + b1);
            float2 v1 = make_float2(acc[mt][nf][2] + b0, acc[mt][nf][3] + b1);
            *(float2*)(g_cand + (size_t)row * MC + n0 + cl)       = v0;
            *(float2*)(g_cand + (size_t)(row + 8) * MC + n0 + cl) = v1;
        }
    }
}

// ---------------- K5: D0 init + barrier reset ------------------------------
__global__ void k5_dinit(const float* __restrict__ base) {
    __shared__ float sh[8];
    int c = blockIdx.x, tid = threadIdx.x;  // 128 threads
    if (c < Bdim && tid == 0) g_bar[c] = 0;
    float s = 0.f;
    for (int m = tid; m < Mdim; m += 128) {
        float v = base[(size_t)m * Cdim + c];
        s += v * v;
    }
    float stot = blockReduceSum(s, sh);
    float inv = 1.f / fmaxf(sqrtf(stot), EPSF);
    for (int b = 0; b < Bdim; b++)
        for (int m = tid; m < Mdim; m += 128)
            g_D[0][((size_t)b * Cdim + c) * Mdim + m] = base[(size_t)m * Cdim + c] * inv;
}

// ---------------- K6: persistent dictionary-update steps + fused output ----
__global__ void __launch_bounds__(256, 2)
k_steps(const float* __restrict__ u, const float* __restrict__ valid,
        const float* __restrict__ Wg, const float* __restrict__ bg,
        float* __restrict__ out) {
    __shared__ float sh[8];
    __shared__ float rsh[Mdim];
    __shared__ float ctsh[Cdim];
    __shared__ float cnd[CPT][CPITCH];
    __shared__ int   aidx[TOPKK];
    __shared__ float aval[TOPKK];
    __shared__ float gsh;
    int tile = blockIdx.x, b = blockIdx.y, tid = threadIdx.x;
    int c0 = tile * CPT;
    int w = tid >> 5, lane = tid & 31;
    int cc = c0 + w;

    for (int t = 0; t < Tdim; t++) {
        int sbuf = t & 1;
        const float* Dsrc = g_D[sbuf];
        float*       Ddst = g_D[sbuf ^ 1];
        int bt = b * Tdim + t;
        const float* ur = u + (size_t)bt * Mdim;
        float vv = valid[bt];
        ctsh[tid] = g_ct[bt * Cdim + tid];
        if (tid < TOPKK) { aidx[tid] = g_aidx[bt * TOPKK + tid]; aval[tid] = g_aval[bt * TOPKK + tid]; }
        __syncthreads();
        float perr = 0.f, pg = 0.f;
        #pragma unroll
        for (int h = 0; h < 2; h++) {
            int m = tid + h * 256;
            float acc = ur[m];
            #pragma unroll
            for (int j = 0; j < TOPKK; j++)
                acc -= Dsrc[((size_t)b * Cdim + aidx[j]) * Mdim + m] * aval[j];
            rsh[m] = acc;
            perr += acc * acc;
            pg   += Wg[m] * ur[m];
        }
        pg += Wg[Mdim + tid] * ctsh[tid];
        // stage cand tile: coalesced float4 loads (c0..c0+7 contiguous 32B)
        const float* cb = g_cand + (size_t)bt * MC + c0;
        #pragma unroll
        for (int it = 0; it < 4; it++) {
            int i = tid + it * 256;
            int m = i >> 1, half = i & 1;
            float4 v = *(const float4*)(cb + (size_t)m * Cdim + half * 4);
            int jb = half * 4;
            cnd[jb + 0][m] = v.x; cnd[jb + 1][m] = v.y;
            cnd[jb + 2][m] = v.z; cnd[jb + 3][m] = v.w;
        }
        float errsum = blockReduceSum(perr, sh);
        float gsum   = blockReduceSum(pg, sh);
        if (tid == 0) {
            float err = sqrtf(errsum);
            float gp  = gsum + Wg[Mdim + Cdim] * err + bg[0];
            gsh = 1.f / (1.f + expf(-gp));
        }
        __syncthreads();
        float g = gsh;
        float av = 0.f;
        #pragma unroll
        for (int j = 0; j < TOPKK; j++)
            if (aidx[j] == cc) av = aval[j];
        const float* Dc = Dsrc + ((size_t)b * Cdim + cc) * Mdim;
        float*       Do = Ddst + ((size_t)b * Cdim + cc) * Mdim;
        float Dreg[16];
        float sl = 0.f, sc2 = 0.f, sx = 0.f;
        float dla = DLRf * av;
        #pragma unroll
        for (int k = 0; k < 16; k++) {
            int m = lane + 32 * k;
            float dd = Dc[m]; Dreg[k] = dd;
            float dl = fmaf(dla, rsh[m], dd);
            float cn = cnd[w][m];
            sl  = fmaf(dl, dl, sl);
            sc2 = fmaf(cn, cn, sc2);
            sx  = fmaf(dl, cn, sx);
        }
        #pragma unroll
        for (int o = 16; o; o >>= 1) {
            sl  += __shfl_xor_sync(0xffffffffu, sl,  o);
            sc2 += __shfl_xor_sync(0xffffffffu, sc2, o);
            sx  += __shfl_xor_sync(0xffffffffu, sx,  o);
        }
        float il  = 1.f / fmaxf(sqrtf(sl),  EPSF);
        float icn = 1.f / fmaxf(sqrtf(sc2), EPSF);
        float w1 = (1.f - g) * il, w2 = g * icn;
        float smix = w1 * w1 * sl + 2.f * w1 * w2 * sx + w2 * w2 * sc2;
        float imix = 1.f / fmaxf(sqrtf(smix), EPSF);
        float ctc = ctsh[cc];
        #pragma unroll
        for (int k = 0; k < 16; k++) {
            int m = lane + 32 * k;
            float dl  = fmaf(dla, rsh[m], Dreg[k]);
            float cn  = cnd[w][m];
            float mix = w1 * dl + w2 * cn;
            float dn  = vv * (mix * imix) + (1.f - vv) * Dreg[k];
            Do[m] = dn;
            cnd[w][m] = dn * ctc;
        }
        __syncthreads();
        float* zp = g_zpart + ((size_t)bt * NTILE + tile) * Mdim;
        for (int m = tid; m < Mdim; m += 256) {
            float z = 0.f;
            #pragma unroll
            for (int j = 0; j < CPT; j++) z += cnd[j][m];
            zp[m] = z;
        }
        __threadfence();
        __syncthreads();
        if (tid == 0) atomicAdd(&g_bar[b], 1u);
        if (t + 1 < Tdim) {
            if (tid == 0) {
                unsigned tgt = (unsigned)((t + 1) * NTILE);
                while (atomicAdd(&g_bar[b], 0u) < tgt) __nanosleep(32);
            }
            __syncthreads();
            __threadfence();
        }
    }
    // ---- fused output: wait for all tiles of batch b, reduce z for one bt --
    if (tid == 0) {
        while (atomicAdd(&g_bar[b], 0u) < (unsigned)(Tdim * NTILE)) __nanosleep(32);
    }
    __syncthreads();
    __threadfence();
    int obt = b * Tdim + tile;       // NTILE == Tdim == 32
    const float* zp = g_zpart + (size_t)obt * NTILE * Mdim;
    for (int m = tid; m < Mdim; m += 256) {
        float s = 0.f;
        #pragma unroll
        for (int j = 0; j < NTILE; j++) s += zp[(size_t)j * Mdim + m];
        out[obt * Mdim + m] = s;
    }
}

// ---------------- launch ---------------------------------------------------
extern "C" void kernel_launch(void* const* d_in, const int* in_sizes, int n_in,
                              void* d_out, int out_size) {
    const float* u       = (const float*)d_in[0];
    const float* valid   = (const float*)d_in[1];
    const float* base    = (const float*)d_in[2];
    const float* Wcu     = (const float*)d_in[3];
    const float* Wcc     = (const float*)d_in[4];
    const float* Wcand_u = (const float*)d_in[5];
    const float* bcand_u = (const float*)d_in[6];
    const float* Wcand_c = (const float*)d_in[7];
    const float* bcand_c = (const float*)d_in[8];
    const float* Wg      = (const float*)d_in[9];
    const float* bg      = (const float*)d_in[10];
    const float* lnug    = (const float*)d_in[11];
    const float* lnub    = (const float*)d_in[12];
    const float* lncg    = (const float*)d_in[13];
    const float* lncb    = (const float*)d_in[14];
    float* out = (float*)d_out;

    cudaFuncSetAttribute(k4_mma, cudaFuncAttributeMaxDynamicSharedMemorySize, K4_SMEM);
    cudaFuncSetAttribute(k3_rec, cudaFuncAttributeMaxDynamicSharedMemorySize, K3_SMEM);

    k5_dinit<<<Cdim, 128>>>(base);
    k1_lnu<<<BT, 256>>>(u, lnug, lnub);
    k2_lu <<<BT, 256>>>(Wcu);
    k3_rec<<<Bdim, 256, K3_SMEM>>>(Wcc, valid, lncg, lncb);
    k_acvt<<<BT, 256>>>();
    k4_mma<<<MC / 64, 256, K4_SMEM>>>(Wcand_u, Wcand_c, bcand_u, bcand_c);
    k_steps<<<dim3(NTILE, Bdim), 256>>>(u, valid, Wg, bg, out);
}